// round 13
// baseline (speedup 1.0000x reference)
#include <cuda_runtime.h>
#include <cuda_fp16.h>
#include <cstdint>
typedef uint32_t u32;

#define B_TOT 4096
#define NCELL 81
#define LN_EPS 1e-5f
#define NTHR 512

__device__ float g_h[NCELL][B_TOT][128];
__device__ float g_c[NCELL][B_TOT][128];
__device__ float g_z [B_TOT][256];
__device__ float g_y1[B_TOT][256];
__device__ float g_y2[B_TOT][128];
__device__ float g_y3[B_TOT];
__device__ float g_mu[256];
__device__ float g_rstd[256];

// pre-converted fp16 hi/lo weights
__device__ __half gWHh[NCELL*49152], gWHl[NCELL*49152];
__device__ __half gWCh[NCELL*49152], gWCl[NCELL*49152];
__device__ __half gWGh[NCELL*65536], gWGl[NCELL*65536];   // gates, row-permuted

__device__ __forceinline__ float sigmf(float v){ return 1.f/(1.f+expf(-v)); }
__device__ __forceinline__ u32 smem_u32(const void* p){
    u32 a; asm("{ .reg .u64 t; cvta.to.shared.u64 t, %1; cvt.u32.u64 %0, t; }" : "=r"(a) : "l"(p)); return a;
}
__device__ __forceinline__ void cpa16(u32 dst, const void* src){
    asm volatile("cp.async.ca.shared.global [%0], [%1], 16;"::"r"(dst),"l"(src));
}
#define CP_COMMIT() asm volatile("cp.async.commit_group;":::"memory")
#define CP_WAIT0()  asm volatile("cp.async.wait_group 0;":::"memory")

// ---- smem byte offsets ----
#define P_BS  0
#define P_WIH 2048
#define P_X   4096
#define P_BH  4352
#define P_BC  4864
#define P_LHG 5376
#define P_LHB 5888
#define P_LCG 6400
#define P_LCB 6912
#define P0 8448            // staging fp32, pitch 132 floats (64 rows): 33792B
#define P1 42240           // ph fp16 chunks: chunk c: hi P1+c*10240, lo +5120 (40960B)
#define P2 83200           // main A/B double buffers; gates B double buffers overlay
#define SMEM_TOTAL 165120
#define AB(i)   (P2 + (i)*10240)             // A: hi 64*80, lo +5120
#define BB(i)   (P2 + 20480 + (i)*20480)     // B: hi 128*80, lo +10240
#define GBUF(i) (P2 + (i)*40960)             // gates B: hi 256*80, lo +20480

__device__ __forceinline__ void mma8(float* d,const u32* a,u32 b0,u32 b1){
    asm volatile("mma.sync.aligned.m16n8k16.row.col.f32.f16.f16.f32 "
        "{%0,%1,%2,%3},{%4,%5,%6,%7},{%8,%9},{%0,%1,%2,%3};"
        : "+f"(d[0]),"+f"(d[1]),"+f"(d[2]),"+f"(d[3])
        : "r"(a[0]),"r"(a[1]),"r"(a[2]),"r"(a[3]),"r"(b0),"r"(b1));
}
__device__ __forceinline__ void cvt2(float ax,float ay,u32&H,u32&L){
    __half2 h=__floats2half2_rn(ax,ay);
    float2 f=__half22float2(h);
    __half2 l=__floats2half2_rn(ax-f.x,ay-f.y);
    H=*(u32*)&h; L=*(u32*)&l;
}

// ---------------- weight conversion pre-pass ----------------
__global__ void conv_main(const float* __restrict__ W, __half* __restrict__ Hh,
                          __half* __restrict__ Hl, int n4){
    int idx=blockIdx.x*blockDim.x+threadIdx.x;
    if(idx>=n4) return;
    float4 v=*(const float4*)(W+(size_t)idx*4);
    u32 h0,l0,h1,l1; cvt2(v.x,v.y,h0,l0); cvt2(v.z,v.w,h1,l1);
    *(uint2*)(Hh+(size_t)idx*4)=make_uint2(h0,h1);
    *(uint2*)(Hl+(size_t)idx*4)=make_uint2(l0,l1);
}
__global__ void conv_gates(const float* __restrict__ W){
    int idx=blockIdx.x*blockDim.x+threadIdx.x;   // over 81*512*32 float4 slots
    if(idx>=NCELL*512*32) return;
    int c4=idx&31; int m=(idx>>5)&511; int k=idx>>14;
    int half=m>>8, mm=m&255, q=mm>>6, gsel=(mm>>5)&1, r=mm&31;
    int base = (half==0) ? (gsel?256:0) : (gsel?384:128);
    int orig = base + 32*q + r;
    float4 v=*(const float4*)(W+(size_t)k*65536+(size_t)orig*128+c4*4);
    u32 h0,l0,h1,l1; cvt2(v.x,v.y,h0,l0); cvt2(v.z,v.w,h1,l1);
    size_t o=(size_t)k*65536+(size_t)m*128+c4*4;
    *(uint2*)(gWGh+o)=make_uint2(h0,h1);
    *(uint2*)(gWGl+o)=make_uint2(l0,l1);
}

// ---------------- main GEMM: [64,384]x[384,128]^T -> P0 fp32 + bias ----------------
__device__ __forceinline__ void main_gemm(char* smc,u32 smb,
    const float* s0,const float* s1,const float* s2,
    const __half* __restrict__ Wh16,const __half* __restrict__ Wl16,
    int b0,int tid,int lane,int w,int biasOff)
{
    const float* srcs[3]={s0,s1,s2};
    float acc[4][4];
#pragma unroll
    for(int s=0;s<4;s++){acc[s][0]=0;acc[s][1]=0;acc[s][2]=0;acc[s][3]=0;}
    float4 rA;
    auto ldA=[&](int kc){
        const float* s=srcs[kc>>2]; int cb=(kc&3)*32;
        int row=tid>>3; int cq=(tid&7)*4;
        rA = s? *(const float4*)(s+(size_t)(b0+row)*128+cb+cq):make_float4(0,0,0,0);
    };
    auto stsA=[&](int buf){
        int row=tid>>3; int cq=(tid&7)*4;
        u32 h0,l0,h1,l1; cvt2(rA.x,rA.y,h0,l0); cvt2(rA.z,rA.w,h1,l1);
        char* p=smc+AB(buf)+row*80+cq*2;
        *(uint2*)p=make_uint2(h0,h1); *(uint2*)(p+5120)=make_uint2(l0,l1);
    };
    auto cpB=[&](int kc,int buf){
        // exactly 512 segments: 128 rows x 4 x 16B; one per thread
        int n=tid>>2; int seg=tid&3;
        u32 d=smb+BB(buf)+n*80+seg*16;
        size_t so=(size_t)768*n + 64*kc + 16*seg;
        cpa16(d,(const char*)Wh16+so);
        cpa16(d+10240,(const char*)Wl16+so);
        CP_COMMIT();
    };
    cpB(0,0); ldA(0); stsA(0); CP_WAIT0(); __syncthreads();
#pragma unroll 1
    for(int kc=0;kc<12;kc++){
        if(kc<11){ cpB(kc+1,(kc+1)&1); ldA(kc+1); }
        const char* Ah=smc+AB(kc&1); const char* Bh=smc+BB(kc&1);
        int ar=16*(w>>2)+(lane>>2);
#pragma unroll
        for(int kh=0;kh<2;kh++){
            int ao=ar*80+(kh*16+(lane&3)*2)*2;
            u32 ah[4],al[4];
            ah[0]=*(const u32*)(Ah+ao);      ah[1]=*(const u32*)(Ah+ao+640);
            ah[2]=*(const u32*)(Ah+ao+16);   ah[3]=*(const u32*)(Ah+ao+656);
            al[0]=*(const u32*)(Ah+ao+5120); al[1]=*(const u32*)(Ah+ao+5760);
            al[2]=*(const u32*)(Ah+ao+5136); al[3]=*(const u32*)(Ah+ao+5776);
#pragma unroll
            for(int s=0;s<4;s++){
                int bn=32*(w&3)+8*s+(lane>>2);
                int bo=bn*80+(kh*16+(lane&3)*2)*2;
                u32 bh0=*(const u32*)(Bh+bo),       bh1=*(const u32*)(Bh+bo+16);
                u32 bl0=*(const u32*)(Bh+bo+10240), bl1=*(const u32*)(Bh+bo+10256);
                mma8(acc[s],ah,bh0,bh1);
                mma8(acc[s],ah,bl0,bl1);
                mma8(acc[s],al,bh0,bh1);
            }
        }
        if(kc<11) stsA((kc+1)&1);
        CP_WAIT0();
        __syncthreads();
    }
    float* pcf=(float*)(smc+P0);
    const float* bias=(const float*)(smc+biasOff);
    int r=16*(w>>2)+(lane>>2);
#pragma unroll
    for(int s=0;s<4;s++){
        int c=32*(w&3)+8*s+(lane&3)*2;
        pcf[r*132+c]=acc[s][0]+bias[c];     pcf[r*132+c+1]=acc[s][1]+bias[c+1];
        pcf[(r+8)*132+c]=acc[s][2]+bias[c]; pcf[(r+8)*132+c+1]=acc[s][3]+bias[c+1];
    }
}

// LN over P0; 16 warps x 4 rows
__device__ __forceinline__ void ln_pass(char* smc,int lane,int w,int gOff,int bOff,int toHalf){
    float* pcf=(float*)(smc+P0);
    const float* g=(const float*)(smc+gOff); const float* b=(const float*)(smc+bOff);
#pragma unroll 1
    for(int rr=0;rr<4;rr++){
        int r=w*4+rr;
        float v[4];
#pragma unroll
        for(int q=0;q<4;q++) v[q]=pcf[r*132+lane+32*q];
        float s=v[0]+v[1]+v[2]+v[3];
        float qq=v[0]*v[0]+v[1]*v[1]+v[2]*v[2]+v[3]*v[3];
#pragma unroll
        for(int o=16;o;o>>=1){ s+=__shfl_xor_sync(~0u,s,o); qq+=__shfl_xor_sync(~0u,qq,o); }
        float mu=s*(1.f/128.f), var=qq*(1.f/128.f)-mu*mu, rs=rsqrtf(var+LN_EPS);
#pragma unroll
        for(int q=0;q<4;q++){
            float nv=(v[q]-mu)*rs*g[lane+32*q]+b[lane+32*q];
            if(toHalf){
                __half hh=__float2half_rn(nv);
                __half hl=__float2half_rn(nv-__half2float(hh));
                *(__half*)(smc+P1+q*10240+r*80+lane*2)=hh;
                *(__half*)(smc+P1+q*10240+5120+r*80+lane*2)=hl;
            } else pcf[r*132+lane+32*q]=nv;
        }
    }
}

__global__ void __launch_bounds__(NTHR) cell_kernel(
    const float* __restrict__ x,
    const float* __restrict__ h_ext,const float* __restrict__ c_ext,
    const float* __restrict__ h_grid0,const float* __restrict__ c_grid0,
    const float* __restrict__ bh,const float* __restrict__ bc,
    const float* __restrict__ lnh_g,const float* __restrict__ lnh_b,
    const float* __restrict__ lnc_g,const float* __restrict__ lnc_b,
    const float* __restrict__ W_ih,const float* __restrict__ b_ih,
    const float* __restrict__ b_hh,int diag)
{
    extern __shared__ char smc[];
    float* smf=(float*)smc;
    u32 smb=smem_u32(smc);
    int tid=threadIdx.x, lane=tid&31, w=tid>>5;
    int b0=blockIdx.x<<6;
    int i0=diag>8?diag-8:0;
    int i=i0+blockIdx.y, j=diag-i, k=i*9+j;

    {
        const float* bihp=b_ih+k*512; const float* bhhp=b_hh+k*512; const float* wihp=W_ih+k*512;
        if(tid<512){ smf[P_BS/4+tid]=bihp[tid]+bhhp[tid]; smf[P_WIH/4+tid]=wihp[tid]; }
        if(tid<64) smf[P_X/4+tid]=x[(size_t)(b0+tid)*81+k];
        if(tid>=128&&tid<256){int t=tid-128;
            smf[P_BH/4+t]=bh[k*128+t];    smf[P_BC/4+t]=bc[k*128+t];
            smf[P_LHG/4+t]=lnh_g[k*128+t];smf[P_LHB/4+t]=lnh_b[k*128+t];
            smf[P_LCG/4+t]=lnc_g[k*128+t];smf[P_LCB/4+t]=lnc_b[k*128+t];
        }
    }
    const float *h0,*c0,*h1,*c1;
    if(j>0){ h0=&g_h[k-1][0][0]; c0=&g_c[k-1][0][0]; }
    else if(i==0){ h0=h_ext; c0=c_ext; }
    else { h0=0; c0=0; }
    if(i>0){ h1=&g_h[k-9][0][0]; c1=&g_c[k-9][0][0]; } else { h1=0; c1=0; }
    const float* h2=h_grid0+(size_t)k*B_TOT*128;
    const float* c2=c_grid0+(size_t)k*B_TOT*128;
    __syncthreads();

    // h GEMM -> LN -> fp16 chunks (gates A)
    main_gemm(smc,smb,h0,h1,h2,gWHh+(size_t)k*49152,gWHl+(size_t)k*49152,b0,tid,lane,w,P_BH);
    __syncthreads();
    ln_pass(smc,lane,w,P_LHG,P_LHB,1);
    __syncthreads();
    // c GEMM -> LN -> fp32 in P0
    main_gemm(smc,smb,c0,c1,c2,gWCh+(size_t)k*49152,gWCl+(size_t)k*49152,b0,tid,lane,w,P_BC);
    __syncthreads();
    ln_pass(smc,lane,w,P_LCG,P_LCB,0);
    __syncthreads();

    // ---- gates: permuted weights; half0=(i,g), half1=(f,o); elementwise in regs ----
    const char* Gh=(const char*)(gWGh+(size_t)k*65536);
    const char* Gl=(const char*)(gWGl+(size_t)k*65536);
    float* pcf=(float*)(smc+P0);
    const float* xs=smf+P_X/4;
    int mw=w&3, nw=w>>2;
    float ac[2][8][4];
#pragma unroll
    for(int hh=0;hh<2;hh++)
#pragma unroll
        for(int s=0;s<8;s++){ac[hh][s][0]=0;ac[hh][s][1]=0;ac[hh][s][2]=0;ac[hh][s][3]=0;}

#pragma unroll 1
    for(int half=0;half<2;half++){
        const char* GhH=Gh+half*65536;
        const char* GlH=Gl+half*65536;
        auto cpG=[&](int kc,int buf){
            // exactly 1024 segments: 256 rows x 4 x 16B; 2 per thread
#pragma unroll
            for(int u=0;u<2;u++){
                int idx=u*NTHR+tid; int m=idx>>2; int seg=idx&3;
                u32 d=smb+GBUF(buf)+m*80+seg*16;
                size_t so=(size_t)256*m + 64*kc + 16*seg;
                cpa16(d,GhH+so);
                cpa16(d+20480,GlH+so);
            }
            CP_COMMIT();
        };
        cpG(0,0); CP_WAIT0(); __syncthreads();
#pragma unroll 1
        for(int kc=0;kc<4;kc++){
            if(kc<3) cpG(kc+1,(kc+1)&1);
            const char* Ah=smc+P1+kc*10240; const char* Bh=smc+GBUF(kc&1);
#pragma unroll
            for(int kh=0;kh<2;kh++){
                int ar=16*mw+(lane>>2);
                int ao=ar*80+(kh*16+(lane&3)*2)*2;
                u32 ah[4],al[4];
                ah[0]=*(const u32*)(Ah+ao);      ah[1]=*(const u32*)(Ah+ao+640);
                ah[2]=*(const u32*)(Ah+ao+16);   ah[3]=*(const u32*)(Ah+ao+656);
                al[0]=*(const u32*)(Ah+ao+5120); al[1]=*(const u32*)(Ah+ao+5760);
                al[2]=*(const u32*)(Ah+ao+5136); al[3]=*(const u32*)(Ah+ao+5776);
#pragma unroll
                for(int s=0;s<8;s++){
                    int bn=64*nw+8*s+(lane>>2);
                    int bo=bn*80+(kh*16+(lane&3)*2)*2;
                    u32 bh0=*(const u32*)(Bh+bo),       bh1=*(const u32*)(Bh+bo+16);
                    u32 bl0=*(const u32*)(Bh+bo+20480), bl1=*(const u32*)(Bh+bo+20496);
                    mma8(ac[half][s],ah,bh0,bh1);
                    mma8(ac[half][s],ah,bl0,bl1);
                    mma8(ac[half][s],al,bh0,bh1);
                }
            }
            CP_WAIT0();
            __syncthreads();
        }
    }

    // elementwise LSTM fully in registers
#pragma unroll
    for(int s=0;s<4;s++){
#pragma unroll
        for(int rr=0;rr<2;rr++){
            int r2=16*mw+(lane>>2)+rr*8;
            float xv=xs[r2];
#pragma unroll
            for(int e=0;e<2;e++){
                int c=32*nw+8*s+(lane&3)*2+e;
                float I=ac[0][s][rr*2+e]  +smf[P_BS/4+c]      +xv*smf[P_WIH/4+c];
                float G=ac[0][s+4][rr*2+e]+smf[P_BS/4+256+c]  +xv*smf[P_WIH/4+256+c];
                float F=ac[1][s][rr*2+e]  +smf[P_BS/4+128+c]  +xv*smf[P_WIH/4+128+c];
                float O=ac[1][s+4][rr*2+e]+smf[P_BS/4+384+c]  +xv*smf[P_WIH/4+384+c];
                float P=pcf[r2*132+c];
                float cn=sigmf(F)*P+sigmf(I)*tanhf(G);
                g_c[k][b0+r2][c]=cn;
                g_h[k][b0+r2][c]=sigmf(O)*tanhf(cn);
            }
        }
    }
}

// ---------------- head kernels ----------------
__global__ void z_kernel(const float* __restrict__ h_ext,const float* __restrict__ c_ext){
    int idx=blockIdx.x*256+threadIdx.x;
    int b=idx>>8, c=idx&255;
    float v;
    if(c<128) v=g_h[80][b][c]+h_ext[b*128+c];
    else      v=g_c[80][b][c-128]+c_ext[b*128+c-128];
    g_z[b][c]=v;
}

__global__ void __launch_bounds__(256,1) head_gemm(
    const float* __restrict__ A,const float* __restrict__ W,
    const float* __restrict__ bias,float* __restrict__ C,int N,int K)
{
    __shared__ float A_s[64*33];
    __shared__ float W_s[128*33];
    int tid=threadIdx.x, ty=tid&15, tx=tid>>4;
    int b0=blockIdx.x*64, n0=blockIdx.y*128;
    float acc[4][8];
#pragma unroll
    for(int r=0;r<4;r++)
#pragma unroll
        for(int c=0;c<8;c++) acc[r][c]=0.f;
    int nk=K>>5;
#pragma unroll 1
    for(int kc=0;kc<nk;kc++){
#pragma unroll
        for(int it=0;it<2;it++){
            int idx=it*256+tid; int r=idx>>3; int c4=(idx&7)<<2;
            float4 v=*(const float4*)(A+(size_t)(b0+r)*K+(kc<<5)+c4);
            float* p=&A_s[r*33+c4]; p[0]=v.x;p[1]=v.y;p[2]=v.z;p[3]=v.w;
        }
#pragma unroll
        for(int it=0;it<4;it++){
            int idx=it*256+tid; int n=idx>>3; int c4=(idx&7)<<2;
            float4 v=*(const float4*)(W+(size_t)(n0+n)*K+(kc<<5)+c4);
            float* p=&W_s[n*33+c4]; p[0]=v.x;p[1]=v.y;p[2]=v.z;p[3]=v.w;
        }
        __syncthreads();
#pragma unroll 4
        for(int kk=0;kk<32;kk++){
            float a[4],wv[8];
#pragma unroll
            for(int r=0;r<4;r++) a[r]=A_s[(ty*4+r)*33+kk];
#pragma unroll
            for(int c=0;c<8;c++) wv[c]=W_s[(tx*8+c)*33+kk];
#pragma unroll
            for(int r=0;r<4;r++)
#pragma unroll
                for(int c=0;c<8;c++) acc[r][c]=fmaf(a[r],wv[c],acc[r][c]);
        }
        __syncthreads();
    }
#pragma unroll
    for(int r=0;r<4;r++)
#pragma unroll
        for(int c=0;c<8;c++)
            C[(size_t)(b0+ty*4+r)*N+n0+tx*8+c]=acc[r][c]+bias[n0+tx*8+c];
}

__global__ void bn_stats_kernel(const float* __restrict__ Y,int N){
    __shared__ float ss[256],qq[256];
    int col=blockIdx.x, tid=threadIdx.x;
    float s=0.f,q=0.f;
    for(int r=tid;r<B_TOT;r+=256){ float v=Y[(size_t)r*N+col]; s+=v; q+=v*v; }
    ss[tid]=s; qq[tid]=q; __syncthreads();
    for(int o=128;o;o>>=1){ if(tid<o){ ss[tid]+=ss[tid+o]; qq[tid]+=qq[tid+o]; } __syncthreads(); }
    if(tid==0){
        float mu=ss[0]*(1.f/(float)B_TOT);
        float var=qq[0]*(1.f/(float)B_TOT)-mu*mu;
        g_mu[col]=mu; g_rstd[col]=rsqrtf(var+LN_EPS);
    }
}

__global__ void bn_relu_kernel(float* __restrict__ Y,const float* __restrict__ g,
                               const float* __restrict__ b,int N){
    int idx=blockIdx.x*256+threadIdx.x;
    int c=idx&(N-1);
    float v=(Y[idx]-g_mu[c])*g_rstd[c]*g[c]+b[c];
    Y[idx]=fmaxf(v,0.f);
}

__global__ void fc3_kernel(const float* __restrict__ W,const float* __restrict__ bias){
    int row=(blockIdx.x*blockDim.x+threadIdx.x)>>5;
    int lane=threadIdx.x&31;
    float s=0.f;
#pragma unroll
    for(int c=lane;c<128;c+=32) s+=g_y2[row][c]*W[c];
#pragma unroll
    for(int o=16;o;o>>=1) s+=__shfl_xor_sync(~0u,s,o);
    if(lane==0) g_y3[row]=s+bias[0];
}

__global__ void final_kernel(const float* __restrict__ g,const float* __restrict__ b,
                             float* __restrict__ out){
    __shared__ float ss[1024],qq[1024];
    int tid=threadIdx.x;
    float s=0.f,q=0.f;
    for(int r=tid;r<B_TOT;r+=1024){ float v=g_y3[r]; s+=v; q+=v*v; }
    ss[tid]=s; qq[tid]=q; __syncthreads();
    for(int o=512;o;o>>=1){ if(tid<o){ ss[tid]+=ss[tid+o]; qq[tid]+=qq[tid+o]; } __syncthreads(); }
    float mu=ss[0]*(1.f/(float)B_TOT);
    float var=qq[0]*(1.f/(float)B_TOT)-mu*mu;
    float rs=rsqrtf(var+LN_EPS);
    float gg=g[0], bb=b[0];
    for(int r=tid;r<B_TOT;r+=1024){
        float v=(g_y3[r]-mu)*rs*gg+bb;
        out[r]=1.f/(1.f+expf(-v));
    }
}

extern "C" void kernel_launch(void* const* d_in,const int* in_sizes,int n_in,
                              void* d_out,int out_size)
{
    const float* x     =(const float*)d_in[0];
    const float* h_ext =(const float*)d_in[1];
    const float* c_ext =(const float*)d_in[2];
    const float* h_g0  =(const float*)d_in[3];
    const float* c_g0  =(const float*)d_in[4];
    const float* Wh    =(const float*)d_in[5];
    const float* bh    =(const float*)d_in[6];
    const float* Wc    =(const float*)d_in[7];
    const float* bc    =(const float*)d_in[8];
    const float* lnh_g =(const float*)d_in[9];
    const float* lnh_b =(const float*)d_in[10];
    const float* lnc_g =(const float*)d_in[11];
    const float* lnc_b =(const float*)d_in[12];
    const float* W_ih  =(const float*)d_in[13];
    const float* b_ih  =(const float*)d_in[14];
    const float* W_hh  =(const float*)d_in[15];
    const float* b_hh  =(const float*)d_in[16];
    const float* fc1W  =(const float*)d_in[17];
    const float* fc1b  =(const float*)d_in[18];
    const float* bn1g  =(const float*)d_in[19];
    const float* bn1b  =(const float*)d_in[20];
    const float* fc2W  =(const float*)d_in[21];
    const float* fc2b  =(const float*)d_in[22];
    const float* bn2g  =(const float*)d_in[23];
    const float* bn2b  =(const float*)d_in[24];
    const float* fc3W  =(const float*)d_in[25];
    const float* fc3b  =(const float*)d_in[26];
    const float* bnog  =(const float*)d_in[27];
    const float* bnob  =(const float*)d_in[28];
    float* out=(float*)d_out;

    // weight pre-conversion
    __half *wHh,*wHl,*wCh,*wCl;
    cudaGetSymbolAddress((void**)&wHh,gWHh); cudaGetSymbolAddress((void**)&wHl,gWHl);
    cudaGetSymbolAddress((void**)&wCh,gWCh); cudaGetSymbolAddress((void**)&wCl,gWCl);
    int n4=NCELL*49152/4;
    conv_main<<<(n4+255)/256,256>>>(Wh,wHh,wHl,n4);
    conv_main<<<(n4+255)/256,256>>>(Wc,wCh,wCl,n4);
    conv_gates<<<(NCELL*512*32+255)/256,256>>>(W_hh);

    cudaFuncSetAttribute(cell_kernel, cudaFuncAttributeMaxDynamicSharedMemorySize, SMEM_TOTAL);

    for(int d=0; d<=16; d++){
        int ilo=d>8?d-8:0, ihi=d<8?d:8;
        int nc=ihi-ilo+1;
        cell_kernel<<<dim3(64,nc), NTHR, SMEM_TOTAL>>>(
            x,h_ext,c_ext,h_g0,c_g0,bh,bc,
            lnh_g,lnh_b,lnc_g,lnc_b,W_ih,b_ih,b_hh,d);
    }

    float *zp,*y1p,*y2p;
    cudaGetSymbolAddress((void**)&zp, g_z);
    cudaGetSymbolAddress((void**)&y1p,g_y1);
    cudaGetSymbolAddress((void**)&y2p,g_y2);

    z_kernel<<<4096,256>>>(h_ext,c_ext);
    head_gemm<<<dim3(64,2),256>>>(zp,fc1W,fc1b,y1p,256,256);
    bn_stats_kernel<<<256,256>>>(y1p,256);
    bn_relu_kernel<<<4096,256>>>(y1p,bn1g,bn1b,256);
    head_gemm<<<dim3(64,1),256>>>(y1p,fc2W,fc2b,y2p,128,256);
    bn_stats_kernel<<<128,256>>>(y2p,128);
    bn_relu_kernel<<<2048,256>>>(y2p,bn2g,bn2b,128);
    fc3_kernel<<<512,256>>>(fc3W,fc3b);
    final_kernel<<<1,1024>>>(bnog,bnob,out);
}

// round 14
// speedup vs baseline: 1.1541x; 1.1541x over previous
#include <cuda_runtime.h>
#include <cuda_fp16.h>
#include <cstdint>
typedef uint32_t u32;

#define B_TOT 4096
#define NCELL 81
#define LN_EPS 1e-5f
#define CNT 256          // cell kernel threads

__device__ float g_h[NCELL][B_TOT][128];
__device__ float g_c[NCELL][B_TOT][128];
__device__ float g_z [B_TOT][256];
__device__ float g_y1[B_TOT][256];
__device__ float g_y2[B_TOT][128];
__device__ float g_y3[B_TOT];
__device__ float g_mu[256];
__device__ float g_rstd[256];

// pre-converted fp16 hi/lo weights
__device__ __half gWHh[NCELL*49152], gWHl[NCELL*49152];
__device__ __half gWCh[NCELL*49152], gWCl[NCELL*49152];
__device__ __half gWGh[NCELL*65536], gWGl[NCELL*65536];   // gates, row-permuted

__device__ __forceinline__ float sigmf(float v){ return 1.f/(1.f+expf(-v)); }
__device__ __forceinline__ u32 smem_u32(const void* p){
    u32 a; asm("{ .reg .u64 t; cvta.to.shared.u64 t, %1; cvt.u32.u64 %0, t; }" : "=r"(a) : "l"(p)); return a;
}
__device__ __forceinline__ void cpa16(u32 dst, const void* src){
    asm volatile("cp.async.ca.shared.global [%0], [%1], 16;"::"r"(dst),"l"(src));
}
#define CP_COMMIT() asm volatile("cp.async.commit_group;":::"memory")
#define CP_WAIT0()  asm volatile("cp.async.wait_group 0;":::"memory")

// ---- smem byte offsets (32-row CTA, total 96000B) ----
#define P_BS  0
#define P_WIH 2048
#define P_X   4096
#define P_BH  4352
#define P_BC  4864
#define P_LHG 5376
#define P_LHB 5888
#define P_LCG 6400
#define P_LCB 6912
#define P0    7424      // staging fp32, 32 rows x pitch 132 floats = 16896B
#define P1    24320     // ph fp16: 4 chunks x (32x80 hi + 32x80 lo) = 4*5120
#define P2    44800     // overlay: main A/B double buf (51200) | gates B single (40960)
#define SMEM_TOTAL 96000
#define AB(i)   (P2 + (i)*5120)              // A: 32x80 hi, lo +2560
#define BB(i)   (P2 + 10240 + (i)*20480)     // B: 128x80 hi, lo +10240
#define GBUF    (P2)                          // gates B: 256x80 hi, lo +20480

__device__ __forceinline__ void mma8(float* d,const u32* a,u32 b0,u32 b1){
    asm volatile("mma.sync.aligned.m16n8k16.row.col.f32.f16.f16.f32 "
        "{%0,%1,%2,%3},{%4,%5,%6,%7},{%8,%9},{%0,%1,%2,%3};"
        : "+f"(d[0]),"+f"(d[1]),"+f"(d[2]),"+f"(d[3])
        : "r"(a[0]),"r"(a[1]),"r"(a[2]),"r"(a[3]),"r"(b0),"r"(b1));
}
__device__ __forceinline__ void cvt2(float ax,float ay,u32&H,u32&L){
    __half2 h=__floats2half2_rn(ax,ay);
    float2 f=__half22float2(h);
    __half2 l=__floats2half2_rn(ax-f.x,ay-f.y);
    H=*(u32*)&h; L=*(u32*)&l;
}

// ---------------- weight conversion pre-pass ----------------
__global__ void conv_main(const float* __restrict__ W, __half* __restrict__ Hh,
                          __half* __restrict__ Hl, int n4){
    int idx=blockIdx.x*blockDim.x+threadIdx.x;
    if(idx>=n4) return;
    float4 v=*(const float4*)(W+(size_t)idx*4);
    u32 h0,l0,h1,l1; cvt2(v.x,v.y,h0,l0); cvt2(v.z,v.w,h1,l1);
    *(uint2*)(Hh+(size_t)idx*4)=make_uint2(h0,h1);
    *(uint2*)(Hl+(size_t)idx*4)=make_uint2(l0,l1);
}
__global__ void conv_gates(const float* __restrict__ W){
    int idx=blockIdx.x*blockDim.x+threadIdx.x;
    if(idx>=NCELL*512*32) return;
    int c4=idx&31; int m=(idx>>5)&511; int k=idx>>14;
    int half=m>>8, mm=m&255, q=mm>>6, gsel=(mm>>5)&1, r=mm&31;
    int base = (half==0) ? (gsel?256:0) : (gsel?384:128);
    int orig = base + 32*q + r;
    float4 v=*(const float4*)(W+(size_t)k*65536+(size_t)orig*128+c4*4);
    u32 h0,l0,h1,l1; cvt2(v.x,v.y,h0,l0); cvt2(v.z,v.w,h1,l1);
    size_t o=(size_t)k*65536+(size_t)m*128+c4*4;
    *(uint2*)(gWGh+o)=make_uint2(h0,h1);
    *(uint2*)(gWGl+o)=make_uint2(l0,l1);
}

// ---------------- main GEMM: [32,384]x[384,128]^T -> P0 fp32 + bias ----------------
__device__ __forceinline__ void main_gemm(char* smc,u32 smb,
    const float* s0,const float* s1,const float* s2,
    const __half* __restrict__ Wh16,const __half* __restrict__ Wl16,
    int b0,int tid,int lane,int w,int biasOff)
{
    const float* srcs[3]={s0,s1,s2};
    float acc[4][4];
#pragma unroll
    for(int s=0;s<4;s++){acc[s][0]=0;acc[s][1]=0;acc[s][2]=0;acc[s][3]=0;}
    float4 rA;
    auto ldA=[&](int kc){
        const float* s=srcs[kc>>2]; int cb=(kc&3)*32;
        int row=tid>>3; int cq=(tid&7)*4;
        rA = s? *(const float4*)(s+(size_t)(b0+row)*128+cb+cq):make_float4(0,0,0,0);
    };
    auto stsA=[&](int buf){
        int row=tid>>3; int cq=(tid&7)*4;
        u32 h0,l0,h1,l1; cvt2(rA.x,rA.y,h0,l0); cvt2(rA.z,rA.w,h1,l1);
        char* p=smc+AB(buf)+row*80+cq*2;
        *(uint2*)p=make_uint2(h0,h1); *(uint2*)(p+2560)=make_uint2(l0,l1);
    };
    auto cpB=[&](int kc,int buf){
        // 512 segments (128 rows x 4 x 16B), 2 per thread
#pragma unroll
        for(int u=0;u<2;u++){
            int idx=u*CNT+tid; int n=idx>>2; int seg=idx&3;
            u32 d=smb+BB(buf)+n*80+seg*16;
            size_t so=(size_t)768*n + 64*kc + 16*seg;
            cpa16(d,(const char*)Wh16+so);
            cpa16(d+10240,(const char*)Wl16+so);
        }
        CP_COMMIT();
    };
    cpB(0,0); ldA(0); stsA(0); CP_WAIT0(); __syncthreads();
#pragma unroll 1
    for(int kc=0;kc<12;kc++){
        if(kc<11){ cpB(kc+1,(kc+1)&1); ldA(kc+1); }
        const char* Ah=smc+AB(kc&1); const char* Bh=smc+BB(kc&1);
        int ar=16*(w>>2)+(lane>>2);
#pragma unroll
        for(int kh=0;kh<2;kh++){
            int ao=ar*80+(kh*16+(lane&3)*2)*2;
            u32 ah[4],al[4];
            ah[0]=*(const u32*)(Ah+ao);      ah[1]=*(const u32*)(Ah+ao+640);
            ah[2]=*(const u32*)(Ah+ao+16);   ah[3]=*(const u32*)(Ah+ao+656);
            al[0]=*(const u32*)(Ah+ao+2560); al[1]=*(const u32*)(Ah+ao+3200);
            al[2]=*(const u32*)(Ah+ao+2576); al[3]=*(const u32*)(Ah+ao+3216);
#pragma unroll
            for(int s=0;s<4;s++){
                int bn=32*(w&3)+8*s+(lane>>2);
                int bo=bn*80+(kh*16+(lane&3)*2)*2;
                u32 bh0=*(const u32*)(Bh+bo),       bh1=*(const u32*)(Bh+bo+16);
                u32 bl0=*(const u32*)(Bh+bo+10240), bl1=*(const u32*)(Bh+bo+10256);
                mma8(acc[s],ah,bh0,bh1);
                mma8(acc[s],ah,bl0,bl1);
                mma8(acc[s],al,bh0,bh1);
            }
        }
        if(kc<11) stsA((kc+1)&1);
        CP_WAIT0();
        __syncthreads();
    }
    float* pcf=(float*)(smc+P0);
    const float* bias=(const float*)(smc+biasOff);
    int r=16*(w>>2)+(lane>>2);
#pragma unroll
    for(int s=0;s<4;s++){
        int c=32*(w&3)+8*s+(lane&3)*2;
        pcf[r*132+c]=acc[s][0]+bias[c];     pcf[r*132+c+1]=acc[s][1]+bias[c+1];
        pcf[(r+8)*132+c]=acc[s][2]+bias[c]; pcf[(r+8)*132+c+1]=acc[s][3]+bias[c+1];
    }
}

// LN over P0; 8 warps x 4 rows = 32 rows
__device__ __forceinline__ void ln_pass(char* smc,int lane,int w,int gOff,int bOff,int toHalf){
    float* pcf=(float*)(smc+P0);
    const float* g=(const float*)(smc+gOff); const float* b=(const float*)(smc+bOff);
#pragma unroll 1
    for(int rr=0;rr<4;rr++){
        int r=w*4+rr;
        float v[4];
#pragma unroll
        for(int q=0;q<4;q++) v[q]=pcf[r*132+lane+32*q];
        float s=v[0]+v[1]+v[2]+v[3];
        float qq=v[0]*v[0]+v[1]*v[1]+v[2]*v[2]+v[3]*v[3];
#pragma unroll
        for(int o=16;o;o>>=1){ s+=__shfl_xor_sync(~0u,s,o); qq+=__shfl_xor_sync(~0u,qq,o); }
        float mu=s*(1.f/128.f), var=qq*(1.f/128.f)-mu*mu, rs=rsqrtf(var+LN_EPS);
#pragma unroll
        for(int q=0;q<4;q++){
            float nv=(v[q]-mu)*rs*g[lane+32*q]+b[lane+32*q];
            if(toHalf){
                __half hh=__float2half_rn(nv);
                __half hl=__float2half_rn(nv-__half2float(hh));
                *(__half*)(smc+P1+q*5120+r*80+lane*2)=hh;
                *(__half*)(smc+P1+q*5120+2560+r*80+lane*2)=hl;
            } else pcf[r*132+lane+32*q]=nv;
        }
    }
}

__global__ void __launch_bounds__(CNT,2) cell_kernel(
    const float* __restrict__ x,
    const float* __restrict__ h_ext,const float* __restrict__ c_ext,
    const float* __restrict__ h_grid0,const float* __restrict__ c_grid0,
    const float* __restrict__ bh,const float* __restrict__ bc,
    const float* __restrict__ lnh_g,const float* __restrict__ lnh_b,
    const float* __restrict__ lnc_g,const float* __restrict__ lnc_b,
    const float* __restrict__ W_ih,const float* __restrict__ b_ih,
    const float* __restrict__ b_hh,int diag)
{
    extern __shared__ char smc[];
    float* smf=(float*)smc;
    u32 smb=smem_u32(smc);
    int tid=threadIdx.x, lane=tid&31, w=tid>>5;
    int b0=blockIdx.x<<5;                // 32 rows per CTA
    int i0=diag>8?diag-8:0;
    int i=i0+blockIdx.y, j=diag-i, k=i*9+j;

    {
        const float* bihp=b_ih+k*512; const float* bhhp=b_hh+k*512; const float* wihp=W_ih+k*512;
#pragma unroll
        for(int u=0;u<2;u++){ int t=u*CNT+tid;
            smf[P_BS/4+t]=bihp[t]+bhhp[t]; smf[P_WIH/4+t]=wihp[t]; }
        if(tid<32) smf[P_X/4+tid]=x[(size_t)(b0+tid)*81+k];
        if(tid>=128&&tid<256){int t=tid-128;
            smf[P_BH/4+t]=bh[k*128+t];    smf[P_BC/4+t]=bc[k*128+t];
            smf[P_LHG/4+t]=lnh_g[k*128+t];smf[P_LHB/4+t]=lnh_b[k*128+t];
            smf[P_LCG/4+t]=lnc_g[k*128+t];smf[P_LCB/4+t]=lnc_b[k*128+t];
        }
    }
    const float *h0,*c0,*h1,*c1;
    if(j>0){ h0=&g_h[k-1][0][0]; c0=&g_c[k-1][0][0]; }
    else if(i==0){ h0=h_ext; c0=c_ext; }
    else { h0=0; c0=0; }
    if(i>0){ h1=&g_h[k-9][0][0]; c1=&g_c[k-9][0][0]; } else { h1=0; c1=0; }
    const float* h2=h_grid0+(size_t)k*B_TOT*128;
    const float* c2=c_grid0+(size_t)k*B_TOT*128;
    __syncthreads();

    // h GEMM -> LN -> fp16 chunks (gates A)
    main_gemm(smc,smb,h0,h1,h2,gWHh+(size_t)k*49152,gWHl+(size_t)k*49152,b0,tid,lane,w,P_BH);
    __syncthreads();
    ln_pass(smc,lane,w,P_LHG,P_LHB,1);
    __syncthreads();
    // c GEMM -> LN -> fp32 in P0
    main_gemm(smc,smb,c0,c1,c2,gWCh+(size_t)k*49152,gWCl+(size_t)k*49152,b0,tid,lane,w,P_BC);
    __syncthreads();
    ln_pass(smc,lane,w,P_LCG,P_LCB,0);
    __syncthreads();

    // ---- gates: permuted weights; halves fully unrolled (static acc indexing) ----
    const char* Gh=(const char*)(gWGh+(size_t)k*65536);
    const char* Gl=(const char*)(gWGl+(size_t)k*65536);
    float* pcf=(float*)(smc+P0);
    const float* xs=smf+P_X/4;
    int mw=w&1, nw=w>>1;
    float ac0[8][4], ac1[8][4];
#pragma unroll
    for(int s=0;s<8;s++){
        ac0[s][0]=0;ac0[s][1]=0;ac0[s][2]=0;ac0[s][3]=0;
        ac1[s][0]=0;ac1[s][1]=0;ac1[s][2]=0;ac1[s][3]=0;
    }
#pragma unroll
    for(int half=0;half<2;half++){
        float (*ac)[4] = half ? ac1 : ac0;
        const char* GhH=Gh+half*65536;
        const char* GlH=Gl+half*65536;
#pragma unroll 1
        for(int kc=0;kc<4;kc++){
            // single-buffered gates B: 1024 segments, 4 per thread
#pragma unroll
            for(int u=0;u<4;u++){
                int idx=u*CNT+tid; int m=idx>>2; int seg=idx&3;
                u32 d=smb+GBUF+m*80+seg*16;
                size_t so=(size_t)256*m + 64*kc + 16*seg;
                cpa16(d,GhH+so);
                cpa16(d+20480,GlH+so);
            }
            CP_COMMIT(); CP_WAIT0();
            __syncthreads();
            const char* Ah=smc+P1+kc*5120; const char* Bh=smc+GBUF;
#pragma unroll
            for(int kh=0;kh<2;kh++){
                int ar=16*mw+(lane>>2);
                int ao=ar*80+(kh*16+(lane&3)*2)*2;
                u32 ah[4],al[4];
                ah[0]=*(const u32*)(Ah+ao);      ah[1]=*(const u32*)(Ah+ao+640);
                ah[2]=*(const u32*)(Ah+ao+16);   ah[3]=*(const u32*)(Ah+ao+656);
                al[0]=*(const u32*)(Ah+ao+2560); al[1]=*(const u32*)(Ah+ao+3200);
                al[2]=*(const u32*)(Ah+ao+2576); al[3]=*(const u32*)(Ah+ao+3216);
#pragma unroll
                for(int s=0;s<8;s++){
                    int bn=64*nw+8*s+(lane>>2);
                    int bo=bn*80+(kh*16+(lane&3)*2)*2;
                    u32 bh0=*(const u32*)(Bh+bo),       bh1=*(const u32*)(Bh+bo+16);
                    u32 bl0=*(const u32*)(Bh+bo+20480), bl1=*(const u32*)(Bh+bo+20496);
                    mma8(ac[s],ah,bh0,bh1);
                    mma8(ac[s],ah,bl0,bl1);
                    mma8(ac[s],al,bh0,bh1);
                }
            }
            __syncthreads();
        }
    }

    // elementwise LSTM fully in registers
#pragma unroll
    for(int s=0;s<4;s++){
#pragma unroll
        for(int rr=0;rr<2;rr++){
            int r2=16*mw+(lane>>2)+rr*8;
            float xv=xs[r2];
#pragma unroll
            for(int e=0;e<2;e++){
                int c=32*nw+8*s+(lane&3)*2+e;
                float I=ac0[s][rr*2+e]  +smf[P_BS/4+c]      +xv*smf[P_WIH/4+c];
                float G=ac0[s+4][rr*2+e]+smf[P_BS/4+256+c]  +xv*smf[P_WIH/4+256+c];
                float F=ac1[s][rr*2+e]  +smf[P_BS/4+128+c]  +xv*smf[P_WIH/4+128+c];
                float O=ac1[s+4][rr*2+e]+smf[P_BS/4+384+c]  +xv*smf[P_WIH/4+384+c];
                float P=pcf[r2*132+c];
                float cn=sigmf(F)*P+sigmf(I)*tanhf(G);
                g_c[k][b0+r2][c]=cn;
                g_h[k][b0+r2][c]=sigmf(O)*tanhf(cn);
            }
        }
    }
}

// ---------------- head kernels ----------------
__global__ void z_kernel(const float* __restrict__ h_ext,const float* __restrict__ c_ext){
    int idx=blockIdx.x*256+threadIdx.x;
    int b=idx>>8, c=idx&255;
    float v;
    if(c<128) v=g_h[80][b][c]+h_ext[b*128+c];
    else      v=g_c[80][b][c-128]+c_ext[b*128+c-128];
    g_z[b][c]=v;
}

__global__ void __launch_bounds__(256,1) head_gemm(
    const float* __restrict__ A,const float* __restrict__ W,
    const float* __restrict__ bias,float* __restrict__ C,int N,int K)
{
    __shared__ float A_s[64*33];
    __shared__ float W_s[128*33];
    int tid=threadIdx.x, ty=tid&15, tx=tid>>4;
    int b0=blockIdx.x*64, n0=blockIdx.y*128;
    float acc[4][8];
#pragma unroll
    for(int r=0;r<4;r++)
#pragma unroll
        for(int c=0;c<8;c++) acc[r][c]=0.f;
    int nk=K>>5;
#pragma unroll 1
    for(int kc=0;kc<nk;kc++){
#pragma unroll
        for(int it=0;it<2;it++){
            int idx=it*256+tid; int r=idx>>3; int c4=(idx&7)<<2;
            float4 v=*(const float4*)(A+(size_t)(b0+r)*K+(kc<<5)+c4);
            float* p=&A_s[r*33+c4]; p[0]=v.x;p[1]=v.y;p[2]=v.z;p[3]=v.w;
        }
#pragma unroll
        for(int it=0;it<4;it++){
            int idx=it*256+tid; int n=idx>>3; int c4=(idx&7)<<2;
            float4 v=*(const float4*)(W+(size_t)(n0+n)*K+(kc<<5)+c4);
            float* p=&W_s[n*33+c4]; p[0]=v.x;p[1]=v.y;p[2]=v.z;p[3]=v.w;
        }
        __syncthreads();
#pragma unroll 4
        for(int kk=0;kk<32;kk++){
            float a[4],wv[8];
#pragma unroll
            for(int r=0;r<4;r++) a[r]=A_s[(ty*4+r)*33+kk];
#pragma unroll
            for(int c=0;c<8;c++) wv[c]=W_s[(tx*8+c)*33+kk];
#pragma unroll
            for(int r=0;r<4;r++)
#pragma unroll
                for(int c=0;c<8;c++) acc[r][c]=fmaf(a[r],wv[c],acc[r][c]);
        }
        __syncthreads();
    }
#pragma unroll
    for(int r=0;r<4;r++)
#pragma unroll
        for(int c=0;c<8;c++)
            C[(size_t)(b0+ty*4+r)*N+n0+tx*8+c]=acc[r][c]+bias[n0+tx*8+c];
}

__global__ void bn_stats_kernel(const float* __restrict__ Y,int N){
    __shared__ float ss[256],qq[256];
    int col=blockIdx.x, tid=threadIdx.x;
    float s=0.f,q=0.f;
    for(int r=tid;r<B_TOT;r+=256){ float v=Y[(size_t)r*N+col]; s+=v; q+=v*v; }
    ss[tid]=s; qq[tid]=q; __syncthreads();
    for(int o=128;o;o>>=1){ if(tid<o){ ss[tid]+=ss[tid+o]; qq[tid]+=qq[tid+o]; } __syncthreads(); }
    if(tid==0){
        float mu=ss[0]*(1.f/(float)B_TOT);
        float var=qq[0]*(1.f/(float)B_TOT)-mu*mu;
        g_mu[col]=mu; g_rstd[col]=rsqrtf(var+LN_EPS);
    }
}

__global__ void bn_relu_kernel(float* __restrict__ Y,const float* __restrict__ g,
                               const float* __restrict__ b,int N){
    int idx=blockIdx.x*256+threadIdx.x;
    int c=idx&(N-1);
    float v=(Y[idx]-g_mu[c])*g_rstd[c]*g[c]+b[c];
    Y[idx]=fmaxf(v,0.f);
}

__global__ void fc3_kernel(const float* __restrict__ W,const float* __restrict__ bias){
    int row=(blockIdx.x*blockDim.x+threadIdx.x)>>5;
    int lane=threadIdx.x&31;
    float s=0.f;
#pragma unroll
    for(int c=lane;c<128;c+=32) s+=g_y2[row][c]*W[c];
#pragma unroll
    for(int o=16;o;o>>=1) s+=__shfl_xor_sync(~0u,s,o);
    if(lane==0) g_y3[row]=s+bias[0];
}

__global__ void final_kernel(const float* __restrict__ g,const float* __restrict__ b,
                             float* __restrict__ out){
    __shared__ float ss[1024],qq[1024];
    int tid=threadIdx.x;
    float s=0.f,q=0.f;
    for(int r=tid;r<B_TOT;r+=1024){ float v=g_y3[r]; s+=v; q+=v*v; }
    ss[tid]=s; qq[tid]=q; __syncthreads();
    for(int o=512;o;o>>=1){ if(tid<o){ ss[tid]+=ss[tid+o]; qq[tid]+=qq[tid+o]; } __syncthreads(); }
    float mu=ss[0]*(1.f/(float)B_TOT);
    float var=qq[0]*(1.f/(float)B_TOT)-mu*mu;
    float rs=rsqrtf(var+LN_EPS);
    float gg=g[0], bb=b[0];
    for(int r=tid;r<B_TOT;r+=1024){
        float v=(g_y3[r]-mu)*rs*gg+bb;
        out[r]=1.f/(1.f+expf(-v));
    }
}

extern "C" void kernel_launch(void* const* d_in,const int* in_sizes,int n_in,
                              void* d_out,int out_size)
{
    const float* x     =(const float*)d_in[0];
    const float* h_ext =(const float*)d_in[1];
    const float* c_ext =(const float*)d_in[2];
    const float* h_g0  =(const float*)d_in[3];
    const float* c_g0  =(const float*)d_in[4];
    const float* Wh    =(const float*)d_in[5];
    const float* bh    =(const float*)d_in[6];
    const float* Wc    =(const float*)d_in[7];
    const float* bc    =(const float*)d_in[8];
    const float* lnh_g =(const float*)d_in[9];
    const float* lnh_b =(const float*)d_in[10];
    const float* lnc_g =(const float*)d_in[11];
    const float* lnc_b =(const float*)d_in[12];
    const float* W_ih  =(const float*)d_in[13];
    const float* b_ih  =(const float*)d_in[14];
    const float* W_hh  =(const float*)d_in[15];
    const float* b_hh  =(const float*)d_in[16];
    const float* fc1W  =(const float*)d_in[17];
    const float* fc1b  =(const float*)d_in[18];
    const float* bn1g  =(const float*)d_in[19];
    const float* bn1b  =(const float*)d_in[20];
    const float* fc2W  =(const float*)d_in[21];
    const float* fc2b  =(const float*)d_in[22];
    const float* bn2g  =(const float*)d_in[23];
    const float* bn2b  =(const float*)d_in[24];
    const float* fc3W  =(const float*)d_in[25];
    const float* fc3b  =(const float*)d_in[26];
    const float* bnog  =(const float*)d_in[27];
    const float* bnob  =(const float*)d_in[28];
    float* out=(float*)d_out;

    // weight pre-conversion
    __half *wHh,*wHl,*wCh,*wCl;
    cudaGetSymbolAddress((void**)&wHh,gWHh); cudaGetSymbolAddress((void**)&wHl,gWHl);
    cudaGetSymbolAddress((void**)&wCh,gWCh); cudaGetSymbolAddress((void**)&wCl,gWCl);
    int n4=NCELL*49152/4;
    conv_main<<<(n4+255)/256,256>>>(Wh,wHh,wHl,n4);
    conv_main<<<(n4+255)/256,256>>>(Wc,wCh,wCl,n4);
    conv_gates<<<(NCELL*512*32+255)/256,256>>>(W_hh);

    cudaFuncSetAttribute(cell_kernel, cudaFuncAttributeMaxDynamicSharedMemorySize, SMEM_TOTAL);

    for(int d=0; d<=16; d++){
        int ilo=d>8?d-8:0, ihi=d<8?d:8;
        int nc=ihi-ilo+1;
        cell_kernel<<<dim3(128,nc), CNT, SMEM_TOTAL>>>(
            x,h_ext,c_ext,h_g0,c_g0,bh,bc,
            lnh_g,lnh_b,lnc_g,lnc_b,W_ih,b_ih,b_hh,d);
    }

    float *zp,*y1p,*y2p;
    cudaGetSymbolAddress((void**)&zp, g_z);
    cudaGetSymbolAddress((void**)&y1p,g_y1);
    cudaGetSymbolAddress((void**)&y2p,g_y2);

    z_kernel<<<4096,256>>>(h_ext,c_ext);
    head_gemm<<<dim3(64,2),256>>>(zp,fc1W,fc1b,y1p,256,256);
    bn_stats_kernel<<<256,256>>>(y1p,256);
    bn_relu_kernel<<<4096,256>>>(y1p,bn1g,bn1b,256);
    head_gemm<<<dim3(64,1),256>>>(y1p,fc2W,fc2b,y2p,128,256);
    bn_stats_kernel<<<128,256>>>(y2p,128);
    bn_relu_kernel<<<2048,256>>>(y2p,bn2g,bn2b,128);
    fc3_kernel<<<512,256>>>(fc3W,fc3b);
    final_kernel<<<1,1024>>>(bnog,bnob,out);
}

// round 15
// speedup vs baseline: 1.3405x; 1.1615x over previous
#include <cuda_runtime.h>
#include <cuda_fp16.h>
#include <cstdint>
typedef uint32_t u32;

#define B_TOT 4096
#define NCELL 81
#define LN_EPS 1e-5f
#define CNT 512

__device__ float g_h[NCELL][B_TOT][128];
__device__ float g_c[NCELL][B_TOT][128];
__device__ float g_z [B_TOT][256];
__device__ float g_y1[B_TOT][256];
__device__ float g_y2[B_TOT][128];
__device__ float g_y3[B_TOT];
__device__ float g_mu[256];
__device__ float g_rstd[256];

__device__ __half gWHh[NCELL*49152], gWHl[NCELL*49152];
__device__ __half gWCh[NCELL*49152], gWCl[NCELL*49152];
__device__ __half gWGh[NCELL*65536], gWGl[NCELL*65536];

__device__ __forceinline__ float sigmf(float v){ return 1.f/(1.f+expf(-v)); }
__device__ __forceinline__ u32 smem_u32(const void* p){
    u32 a; asm("{ .reg .u64 t; cvta.to.shared.u64 t, %1; cvt.u32.u64 %0, t; }" : "=r"(a) : "l"(p)); return a;
}
__device__ __forceinline__ void cpa16(u32 dst, const void* src){
    asm volatile("cp.async.ca.shared.global [%0], [%1], 16;"::"r"(dst),"l"(src));
}
#define CP_COMMIT() asm volatile("cp.async.commit_group;":::"memory")
#define CP_WAIT0()  asm volatile("cp.async.wait_group 0;":::"memory")

// ---- smem byte offsets (64-row CTA) ----
#define P_BS  0
#define P_WIH 2048
#define P_X   4096
#define P_BH  4352
#define P_BC  4864
#define P_LHG 5376
#define P_LHB 5888
#define P_LCG 6400
#define P_LCB 6912
#define P0    7424      // fp32 staging 64 x 132 = 33792B
#define P1    41216     // ph fp16: 4 chunks x (64x80 hi + 64x80 lo) = 40960B
#define P2    82176     // overlay: main A/B (110592) | gates B double buf (81920)
#define SMEM_TOTAL 192768
#define AB(i)   (P2 + (i)*18432)              // A: 64x144 hi, lo +9216
#define BB(i)   (P2 + 36864 + (i)*36864)      // B: 128x144 hi, lo +18432
#define GBUF(i) (P2 + (i)*40960)              // gates B: 256x80 hi, lo +20480

__device__ __forceinline__ void mma8(float* d,const u32* a,u32 b0,u32 b1){
    asm volatile("mma.sync.aligned.m16n8k16.row.col.f32.f16.f16.f32 "
        "{%0,%1,%2,%3},{%4,%5,%6,%7},{%8,%9},{%0,%1,%2,%3};"
        : "+f"(d[0]),"+f"(d[1]),"+f"(d[2]),"+f"(d[3])
        : "r"(a[0]),"r"(a[1]),"r"(a[2]),"r"(a[3]),"r"(b0),"r"(b1));
}
__device__ __forceinline__ void cvt2(float ax,float ay,u32&H,u32&L){
    __half2 h=__floats2half2_rn(ax,ay);
    float2 f=__half22float2(h);
    __half2 l=__floats2half2_rn(ax-f.x,ay-f.y);
    H=*(u32*)&h; L=*(u32*)&l;
}

// ---------------- weight conversion pre-pass ----------------
__global__ void conv_main(const float* __restrict__ W, __half* __restrict__ Hh,
                          __half* __restrict__ Hl, int n4){
    int idx=blockIdx.x*blockDim.x+threadIdx.x;
    if(idx>=n4) return;
    float4 v=*(const float4*)(W+(size_t)idx*4);
    u32 h0,l0,h1,l1; cvt2(v.x,v.y,h0,l0); cvt2(v.z,v.w,h1,l1);
    *(uint2*)(Hh+(size_t)idx*4)=make_uint2(h0,h1);
    *(uint2*)(Hl+(size_t)idx*4)=make_uint2(l0,l1);
}
__global__ void conv_gates(const float* __restrict__ W){
    int idx=blockIdx.x*blockDim.x+threadIdx.x;
    if(idx>=NCELL*512*32) return;
    int c4=idx&31; int m=(idx>>5)&511; int k=idx>>14;
    int half=m>>8, mm=m&255, q=mm>>6, gsel=(mm>>5)&1, r=mm&31;
    int base = (half==0) ? (gsel?256:0) : (gsel?384:128);
    int orig = base + 32*q + r;
    float4 v=*(const float4*)(W+(size_t)k*65536+(size_t)orig*128+c4*4);
    u32 h0,l0,h1,l1; cvt2(v.x,v.y,h0,l0); cvt2(v.z,v.w,h1,l1);
    size_t o=(size_t)k*65536+(size_t)m*128+c4*4;
    *(uint2*)(gWGh+o)=make_uint2(h0,h1);
    *(uint2*)(gWGl+o)=make_uint2(l0,l1);
}

// -------- main GEMM: [64,384]x[384,128]^T -> P0 fp32 + bias. K-chunk = 64 --------
__device__ __forceinline__ void main_gemm(char* smc,u32 smb,
    const float* s0,const float* s1,const float* s2,
    const __half* __restrict__ Wh16,const __half* __restrict__ Wl16,
    int b0,int tid,int lane,int w,int biasOff)
{
    const float* srcs[3]={s0,s1,s2};
    float acc[4][4];
#pragma unroll
    for(int s=0;s<4;s++){acc[s][0]=0;acc[s][1]=0;acc[s][2]=0;acc[s][3]=0;}
    float4 rA[2];
    auto ldA=[&](int kc){
        const float* s=srcs[kc>>1]; int cb=(kc&1)*64;
#pragma unroll
        for(int u=0;u<2;u++){
            int slot=u*CNT+tid; int row=slot>>4; int cq=(slot&15)*4;
            rA[u]= s? *(const float4*)(s+(size_t)(b0+row)*128+cb+cq):make_float4(0,0,0,0);
        }
    };
    auto stsA=[&](int buf){
#pragma unroll
        for(int u=0;u<2;u++){
            int slot=u*CNT+tid; int row=slot>>4; int cq=(slot&15)*4;
            u32 h0,l0,h1,l1; cvt2(rA[u].x,rA[u].y,h0,l0); cvt2(rA[u].z,rA[u].w,h1,l1);
            char* p=smc+AB(buf)+row*144+cq*2;
            *(uint2*)p=make_uint2(h0,h1); *(uint2*)(p+9216)=make_uint2(l0,l1);
        }
    };
    auto cpB=[&](int kc,int buf){
        // 1024 segments (128 rows x 8 x 16B), 2 per thread (hi+lo each)
#pragma unroll
        for(int u=0;u<2;u++){
            int idx=u*CNT+tid; int n=idx>>3; int seg=idx&7;
            u32 d=smb+BB(buf)+n*144+seg*16;
            size_t so=(size_t)768*n + 128*kc + 16*seg;
            cpa16(d,(const char*)Wh16+so);
            cpa16(d+18432,(const char*)Wl16+so);
        }
        CP_COMMIT();
    };
    cpB(0,0); ldA(0); stsA(0); CP_WAIT0(); __syncthreads();
#pragma unroll 1
    for(int kc=0;kc<6;kc++){
        if(kc<5){ cpB(kc+1,(kc+1)&1); ldA(kc+1); }
        const char* Ah=smc+AB(kc&1); const char* Bh=smc+BB(kc&1);
        int ar=16*(w>>2)+(lane>>2);
#pragma unroll
        for(int kh=0;kh<4;kh++){
            int ao=ar*144+(kh*16+(lane&3)*2)*2;
            u32 ah[4],al[4];
            ah[0]=*(const u32*)(Ah+ao);      ah[1]=*(const u32*)(Ah+ao+1152);
            ah[2]=*(const u32*)(Ah+ao+16);   ah[3]=*(const u32*)(Ah+ao+1168);
            al[0]=*(const u32*)(Ah+ao+9216); al[1]=*(const u32*)(Ah+ao+10368);
            al[2]=*(const u32*)(Ah+ao+9232); al[3]=*(const u32*)(Ah+ao+10384);
#pragma unroll
            for(int s=0;s<4;s++){
                int bn=32*(w&3)+8*s+(lane>>2);
                int bo=bn*144+(kh*16+(lane&3)*2)*2;
                u32 bh0=*(const u32*)(Bh+bo),       bh1=*(const u32*)(Bh+bo+16);
                u32 bl0=*(const u32*)(Bh+bo+18432), bl1=*(const u32*)(Bh+bo+18448);
                mma8(acc[s],ah,bh0,bh1);
                mma8(acc[s],ah,bl0,bl1);
                mma8(acc[s],al,bh0,bh1);
            }
        }
        if(kc<5) stsA((kc+1)&1);
        CP_WAIT0();
        __syncthreads();
    }
    float* pcf=(float*)(smc+P0);
    const float* bias=(const float*)(smc+biasOff);
    int r=16*(w>>2)+(lane>>2);
#pragma unroll
    for(int s=0;s<4;s++){
        int c=32*(w&3)+8*s+(lane&3)*2;
        pcf[r*132+c]=acc[s][0]+bias[c];     pcf[r*132+c+1]=acc[s][1]+bias[c+1];
        pcf[(r+8)*132+c]=acc[s][2]+bias[c]; pcf[(r+8)*132+c+1]=acc[s][3]+bias[c+1];
    }
}

// LN over P0; 16 warps x 4 rows = 64 rows
__device__ __forceinline__ void ln_pass(char* smc,int lane,int w,int gOff,int bOff,int toHalf){
    float* pcf=(float*)(smc+P0);
    const float* g=(const float*)(smc+gOff); const float* b=(const float*)(smc+bOff);
#pragma unroll 1
    for(int rr=0;rr<4;rr++){
        int r=w*4+rr;
        float v[4];
#pragma unroll
        for(int q=0;q<4;q++) v[q]=pcf[r*132+lane+32*q];
        float s=v[0]+v[1]+v[2]+v[3];
        float qq=v[0]*v[0]+v[1]*v[1]+v[2]*v[2]+v[3]*v[3];
#pragma unroll
        for(int o=16;o;o>>=1){ s+=__shfl_xor_sync(~0u,s,o); qq+=__shfl_xor_sync(~0u,qq,o); }
        float mu=s*(1.f/128.f), var=qq*(1.f/128.f)-mu*mu, rs=rsqrtf(var+LN_EPS);
#pragma unroll
        for(int q=0;q<4;q++){
            float nv=(v[q]-mu)*rs*g[lane+32*q]+b[lane+32*q];
            if(toHalf){
                __half hh=__float2half_rn(nv);
                __half hl=__float2half_rn(nv-__half2float(hh));
                *(__half*)(smc+P1+q*10240+r*80+lane*2)=hh;
                *(__half*)(smc+P1+q*10240+5120+r*80+lane*2)=hl;
            } else pcf[r*132+lane+32*q]=nv;
        }
    }
}

__global__ void __launch_bounds__(CNT,1) cell_kernel(
    const float* __restrict__ x,
    const float* __restrict__ h_ext,const float* __restrict__ c_ext,
    const float* __restrict__ h_grid0,const float* __restrict__ c_grid0,
    const float* __restrict__ bh,const float* __restrict__ bc,
    const float* __restrict__ lnh_g,const float* __restrict__ lnh_b,
    const float* __restrict__ lnc_g,const float* __restrict__ lnc_b,
    const float* __restrict__ W_ih,const float* __restrict__ b_ih,
    const float* __restrict__ b_hh,int diag)
{
    extern __shared__ char smc[];
    float* smf=(float*)smc;
    u32 smb=smem_u32(smc);
    int tid=threadIdx.x, lane=tid&31, w=tid>>5;
    int b0=blockIdx.x<<6;                // 64 rows per CTA
    int i0=diag>8?diag-8:0;
    int i=i0+blockIdx.y, j=diag-i, k=i*9+j;

    {
        const float* bihp=b_ih+k*512; const float* bhhp=b_hh+k*512; const float* wihp=W_ih+k*512;
        if(tid<512){ smf[P_BS/4+tid]=bihp[tid]+bhhp[tid]; smf[P_WIH/4+tid]=wihp[tid]; }
        if(tid<64) smf[P_X/4+tid]=x[(size_t)(b0+tid)*81+k];
        if(tid>=128&&tid<256){int t=tid-128;
            smf[P_BH/4+t]=bh[k*128+t];    smf[P_BC/4+t]=bc[k*128+t];
            smf[P_LHG/4+t]=lnh_g[k*128+t];smf[P_LHB/4+t]=lnh_b[k*128+t];
            smf[P_LCG/4+t]=lnc_g[k*128+t];smf[P_LCB/4+t]=lnc_b[k*128+t];
        }
    }
    const float *h0,*c0,*h1,*c1;
    if(j>0){ h0=&g_h[k-1][0][0]; c0=&g_c[k-1][0][0]; }
    else if(i==0){ h0=h_ext; c0=c_ext; }
    else { h0=0; c0=0; }
    if(i>0){ h1=&g_h[k-9][0][0]; c1=&g_c[k-9][0][0]; } else { h1=0; c1=0; }
    const float* h2=h_grid0+(size_t)k*B_TOT*128;
    const float* c2=c_grid0+(size_t)k*B_TOT*128;
    __syncthreads();

    // h GEMM -> LN -> fp16 chunks (gates A)
    main_gemm(smc,smb,h0,h1,h2,gWHh+(size_t)k*49152,gWHl+(size_t)k*49152,b0,tid,lane,w,P_BH);
    __syncthreads();
    ln_pass(smc,lane,w,P_LHG,P_LHB,1);
    __syncthreads();
    // c GEMM -> LN -> fp32 in P0
    main_gemm(smc,smb,c0,c1,c2,gWCh+(size_t)k*49152,gWCl+(size_t)k*49152,b0,tid,lane,w,P_BC);
    __syncthreads();
    ln_pass(smc,lane,w,P_LCG,P_LCB,0);
    __syncthreads();

    // ---- gates: permuted weights; halves fully unrolled; double-buffered B ----
    const char* Gh=(const char*)(gWGh+(size_t)k*65536);
    const char* Gl=(const char*)(gWGl+(size_t)k*65536);
    float* pcf=(float*)(smc+P0);
    const float* xs=smf+P_X/4;
    int mw=w&3, nw=w>>2;
    float ac0[8][4], ac1[8][4];
#pragma unroll
    for(int s=0;s<8;s++){
        ac0[s][0]=0;ac0[s][1]=0;ac0[s][2]=0;ac0[s][3]=0;
        ac1[s][0]=0;ac1[s][1]=0;ac1[s][2]=0;ac1[s][3]=0;
    }
#pragma unroll
    for(int half=0;half<2;half++){
        float (*ac)[4] = half ? ac1 : ac0;
        const char* GhH=Gh+half*65536;
        const char* GlH=Gl+half*65536;
        auto cpG=[&](int kc,int buf){
            // 1024 segments (256 rows x 4 x 16B), 2 per thread
#pragma unroll
            for(int u=0;u<2;u++){
                int idx=u*CNT+tid; int m=idx>>2; int seg=idx&3;
                u32 d=smb+GBUF(buf)+m*80+seg*16;
                size_t so=(size_t)256*m + 64*kc + 16*seg;
                cpa16(d,GhH+so);
                cpa16(d+20480,GlH+so);
            }
            CP_COMMIT();
        };
        cpG(0,0); CP_WAIT0(); __syncthreads();
#pragma unroll 1
        for(int kc=0;kc<4;kc++){
            if(kc<3) cpG(kc+1,(kc+1)&1);
            const char* Ah=smc+P1+kc*10240; const char* Bh=smc+GBUF(kc&1);
#pragma unroll
            for(int kh=0;kh<2;kh++){
                int ar=16*mw+(lane>>2);
                int ao=ar*80+(kh*16+(lane&3)*2)*2;
                u32 ah[4],al[4];
                ah[0]=*(const u32*)(Ah+ao);      ah[1]=*(const u32*)(Ah+ao+640);
                ah[2]=*(const u32*)(Ah+ao+16);   ah[3]=*(const u32*)(Ah+ao+656);
                al[0]=*(const u32*)(Ah+ao+5120); al[1]=*(const u32*)(Ah+ao+5760);
                al[2]=*(const u32*)(Ah+ao+5136); al[3]=*(const u32*)(Ah+ao+5776);
#pragma unroll
                for(int s=0;s<8;s++){
                    int bn=64*nw+8*s+(lane>>2);
                    int bo=bn*80+(kh*16+(lane&3)*2)*2;
                    u32 bh0=*(const u32*)(Bh+bo),       bh1=*(const u32*)(Bh+bo+16);
                    u32 bl0=*(const u32*)(Bh+bo+20480), bl1=*(const u32*)(Bh+bo+20496);
                    mma8(ac[s],ah,bh0,bh1);
                    mma8(ac[s],ah,bl0,bl1);
                    mma8(ac[s],al,bh0,bh1);
                }
            }
            CP_WAIT0();
            __syncthreads();
        }
    }

    // elementwise LSTM fully in registers
#pragma unroll
    for(int s=0;s<4;s++){
#pragma unroll
        for(int rr=0;rr<2;rr++){
            int r2=16*mw+(lane>>2)+rr*8;
            float xv=xs[r2];
#pragma unroll
            for(int e=0;e<2;e++){
                int c=32*nw+8*s+(lane&3)*2+e;
                float I=ac0[s][rr*2+e]  +smf[P_BS/4+c]      +xv*smf[P_WIH/4+c];
                float G=ac0[s+4][rr*2+e]+smf[P_BS/4+256+c]  +xv*smf[P_WIH/4+256+c];
                float F=ac1[s][rr*2+e]  +smf[P_BS/4+128+c]  +xv*smf[P_WIH/4+128+c];
                float O=ac1[s+4][rr*2+e]+smf[P_BS/4+384+c]  +xv*smf[P_WIH/4+384+c];
                float P=pcf[r2*132+c];
                float cn=sigmf(F)*P+sigmf(I)*tanhf(G);
                g_c[k][b0+r2][c]=cn;
                g_h[k][b0+r2][c]=sigmf(O)*tanhf(cn);
            }
        }
    }
}

// ---------------- head kernels ----------------
__global__ void z_kernel(const float* __restrict__ h_ext,const float* __restrict__ c_ext){
    int idx=blockIdx.x*256+threadIdx.x;
    int b=idx>>8, c=idx&255;
    float v;
    if(c<128) v=g_h[80][b][c]+h_ext[b*128+c];
    else      v=g_c[80][b][c-128]+c_ext[b*128+c-128];
    g_z[b][c]=v;
}

__global__ void __launch_bounds__(256,1) head_gemm(
    const float* __restrict__ A,const float* __restrict__ W,
    const float* __restrict__ bias,float* __restrict__ C,int N,int K)
{
    __shared__ float A_s[64*33];
    __shared__ float W_s[128*33];
    int tid=threadIdx.x, ty=tid&15, tx=tid>>4;
    int b0=blockIdx.x*64, n0=blockIdx.y*128;
    float acc[4][8];
#pragma unroll
    for(int r=0;r<4;r++)
#pragma unroll
        for(int c=0;c<8;c++) acc[r][c]=0.f;
    int nk=K>>5;
#pragma unroll 1
    for(int kc=0;kc<nk;kc++){
#pragma unroll
        for(int it=0;it<2;it++){
            int idx=it*256+tid; int r=idx>>3; int c4=(idx&7)<<2;
            float4 v=*(const float4*)(A+(size_t)(b0+r)*K+(kc<<5)+c4);
            float* p=&A_s[r*33+c4]; p[0]=v.x;p[1]=v.y;p[2]=v.z;p[3]=v.w;
        }
#pragma unroll
        for(int it=0;it<4;it++){
            int idx=it*256+tid; int n=idx>>3; int c4=(idx&7)<<2;
            float4 v=*(const float4*)(W+(size_t)(n0+n)*K+(kc<<5)+c4);
            float* p=&W_s[n*33+c4]; p[0]=v.x;p[1]=v.y;p[2]=v.z;p[3]=v.w;
        }
        __syncthreads();
#pragma unroll 4
        for(int kk=0;kk<32;kk++){
            float a[4],wv[8];
#pragma unroll
            for(int r=0;r<4;r++) a[r]=A_s[(ty*4+r)*33+kk];
#pragma unroll
            for(int c=0;c<8;c++) wv[c]=W_s[(tx*8+c)*33+kk];
#pragma unroll
            for(int r=0;r<4;r++)
#pragma unroll
                for(int c=0;c<8;c++) acc[r][c]=fmaf(a[r],wv[c],acc[r][c]);
        }
        __syncthreads();
    }
#pragma unroll
    for(int r=0;r<4;r++)
#pragma unroll
        for(int c=0;c<8;c++)
            C[(size_t)(b0+ty*4+r)*N+n0+tx*8+c]=acc[r][c]+bias[n0+tx*8+c];
}

__global__ void bn_stats_kernel(const float* __restrict__ Y,int N){
    __shared__ float ss[256],qq[256];
    int col=blockIdx.x, tid=threadIdx.x;
    float s=0.f,q=0.f;
    for(int r=tid;r<B_TOT;r+=256){ float v=Y[(size_t)r*N+col]; s+=v; q+=v*v; }
    ss[tid]=s; qq[tid]=q; __syncthreads();
    for(int o=128;o;o>>=1){ if(tid<o){ ss[tid]+=ss[tid+o]; qq[tid]+=qq[tid+o]; } __syncthreads(); }
    if(tid==0){
        float mu=ss[0]*(1.f/(float)B_TOT);
        float var=qq[0]*(1.f/(float)B_TOT)-mu*mu;
        g_mu[col]=mu; g_rstd[col]=rsqrtf(var+LN_EPS);
    }
}

__global__ void bn_relu_kernel(float* __restrict__ Y,const float* __restrict__ g,
                               const float* __restrict__ b,int N){
    int idx=blockIdx.x*256+threadIdx.x;
    int c=idx&(N-1);
    float v=(Y[idx]-g_mu[c])*g_rstd[c]*g[c]+b[c];
    Y[idx]=fmaxf(v,0.f);
}

__global__ void fc3_kernel(const float* __restrict__ W,const float* __restrict__ bias){
    int row=(blockIdx.x*blockDim.x+threadIdx.x)>>5;
    int lane=threadIdx.x&31;
    float s=0.f;
#pragma unroll
    for(int c=lane;c<128;c+=32) s+=g_y2[row][c]*W[c];
#pragma unroll
    for(int o=16;o;o>>=1) s+=__shfl_xor_sync(~0u,s,o);
    if(lane==0) g_y3[row]=s+bias[0];
}

__global__ void final_kernel(const float* __restrict__ g,const float* __restrict__ b,
                             float* __restrict__ out){
    __shared__ float ss[1024],qq[1024];
    int tid=threadIdx.x;
    float s=0.f,q=0.f;
    for(int r=tid;r<B_TOT;r+=1024){ float v=g_y3[r]; s+=v; q+=v*v; }
    ss[tid]=s; qq[tid]=q; __syncthreads();
    for(int o=512;o;o>>=1){ if(tid<o){ ss[tid]+=ss[tid+o]; qq[tid]+=qq[tid+o]; } __syncthreads(); }
    float mu=ss[0]*(1.f/(float)B_TOT);
    float var=qq[0]*(1.f/(float)B_TOT)-mu*mu;
    float rs=rsqrtf(var+LN_EPS);
    float gg=g[0], bb=b[0];
    for(int r=tid;r<B_TOT;r+=1024){
        float v=(g_y3[r]-mu)*rs*gg+bb;
        out[r]=1.f/(1.f+expf(-v));
    }
}

extern "C" void kernel_launch(void* const* d_in,const int* in_sizes,int n_in,
                              void* d_out,int out_size)
{
    const float* x     =(const float*)d_in[0];
    const float* h_ext =(const float*)d_in[1];
    const float* c_ext =(const float*)d_in[2];
    const float* h_g0  =(const float*)d_in[3];
    const float* c_g0  =(const float*)d_in[4];
    const float* Wh    =(const float*)d_in[5];
    const float* bh    =(const float*)d_in[6];
    const float* Wc    =(const float*)d_in[7];
    const float* bc    =(const float*)d_in[8];
    const float* lnh_g =(const float*)d_in[9];
    const float* lnh_b =(const float*)d_in[10];
    const float* lnc_g =(const float*)d_in[11];
    const float* lnc_b =(const float*)d_in[12];
    const float* W_ih  =(const float*)d_in[13];
    const float* b_ih  =(const float*)d_in[14];
    const float* W_hh  =(const float*)d_in[15];
    const float* b_hh  =(const float*)d_in[16];
    const float* fc1W  =(const float*)d_in[17];
    const float* fc1b  =(const float*)d_in[18];
    const float* bn1g  =(const float*)d_in[19];
    const float* bn1b  =(const float*)d_in[20];
    const float* fc2W  =(const float*)d_in[21];
    const float* fc2b  =(const float*)d_in[22];
    const float* bn2g  =(const float*)d_in[23];
    const float* bn2b  =(const float*)d_in[24];
    const float* fc3W  =(const float*)d_in[25];
    const float* fc3b  =(const float*)d_in[26];
    const float* bnog  =(const float*)d_in[27];
    const float* bnob  =(const float*)d_in[28];
    float* out=(float*)d_out;

    __half *wHh,*wHl,*wCh,*wCl;
    cudaGetSymbolAddress((void**)&wHh,gWHh); cudaGetSymbolAddress((void**)&wHl,gWHl);
    cudaGetSymbolAddress((void**)&wCh,gWCh); cudaGetSymbolAddress((void**)&wCl,gWCl);
    int n4=NCELL*49152/4;
    conv_main<<<(n4+255)/256,256>>>(Wh,wHh,wHl,n4);
    conv_main<<<(n4+255)/256,256>>>(Wc,wCh,wCl,n4);
    conv_gates<<<(NCELL*512*32+255)/256,256>>>(W_hh);

    cudaFuncSetAttribute(cell_kernel, cudaFuncAttributeMaxDynamicSharedMemorySize, SMEM_TOTAL);

    for(int d=0; d<=16; d++){
        int ilo=d>8?d-8:0, ihi=d<8?d:8;
        int nc=ihi-ilo+1;
        cell_kernel<<<dim3(64,nc), CNT, SMEM_TOTAL>>>(
            x,h_ext,c_ext,h_g0,c_g0,bh,bc,
            lnh_g,lnh_b,lnc_g,lnc_b,W_ih,b_ih,b_hh,d);
    }

    float *zp,*y1p,*y2p;
    cudaGetSymbolAddress((void**)&zp, g_z);
    cudaGetSymbolAddress((void**)&y1p,g_y1);
    cudaGetSymbolAddress((void**)&y2p,g_y2);

    z_kernel<<<4096,256>>>(h_ext,c_ext);
    head_gemm<<<dim3(64,2),256>>>(zp,fc1W,fc1b,y1p,256,256);
    bn_stats_kernel<<<256,256>>>(y1p,256);
    bn_relu_kernel<<<4096,256>>>(y1p,bn1g,bn1b,256);
    head_gemm<<<dim3(64,1),256>>>(y1p,fc2W,fc2b,y2p,128,256);
    bn_stats_kernel<<<128,256>>>(y2p,128);
    bn_relu_kernel<<<2048,256>>>(y2p,bn2g,bn2b,128);
    fc3_kernel<<<512,256>>>(fc3W,fc3b);
    final_kernel<<<1,1024>>>(bnog,bnob,out);
}

// round 16
// speedup vs baseline: 1.4691x; 1.0960x over previous
#include <cuda_runtime.h>
#include <cuda_fp16.h>
#include <cstdint>
typedef uint32_t u32;

#define B_TOT 4096
#define NCELL 81
#define LN_EPS 1e-5f
#define CNT 512
#define NTASK (NCELL*64)

__device__ float g_h[NCELL][B_TOT][128];
__device__ float g_c[NCELL][B_TOT][128];
__device__ float g_z [B_TOT][256];
__device__ float g_y1[B_TOT][256];
__device__ float g_y2[B_TOT][128];
__device__ float g_y3[B_TOT];
__device__ float g_mu[256];
__device__ float g_rstd[256];
__device__ int g_flag[NTASK];
__device__ unsigned int g_task;

__device__ __half gWHh[NCELL*49152], gWHl[NCELL*49152];
__device__ __half gWCh[NCELL*49152], gWCl[NCELL*49152];
__device__ __half gWGh[NCELL*65536], gWGl[NCELL*65536];

__device__ __forceinline__ float sigmf(float v){ return 1.f/(1.f+expf(-v)); }
__device__ __forceinline__ u32 smem_u32(const void* p){
    u32 a; asm("{ .reg .u64 t; cvta.to.shared.u64 t, %1; cvt.u32.u64 %0, t; }" : "=r"(a) : "l"(p)); return a;
}
__device__ __forceinline__ void cpa16(u32 dst, const void* src){
    asm volatile("cp.async.ca.shared.global [%0], [%1], 16;"::"r"(dst),"l"(src));
}
#define CP_COMMIT() asm volatile("cp.async.commit_group;":::"memory")
#define CP_WAIT0()  asm volatile("cp.async.wait_group 0;":::"memory")

// ---- smem byte offsets (64-row CTA) ----
#define P_BS  0
#define P_WIH 2048
#define P_X   4096
#define P_BH  4352
#define P_BC  4864
#define P_LHG 5376
#define P_LHB 5888
#define P_LCG 6400
#define P_LCB 6912
#define P0    7424
#define P1    41216
#define P2    82176
#define SMEM_TOTAL 192768
#define AB(i)   (P2 + (i)*18432)
#define BB(i)   (P2 + 36864 + (i)*36864)
#define GBUF(i) (P2 + (i)*40960)

__device__ __forceinline__ void mma8(float* d,const u32* a,u32 b0,u32 b1){
    asm volatile("mma.sync.aligned.m16n8k16.row.col.f32.f16.f16.f32 "
        "{%0,%1,%2,%3},{%4,%5,%6,%7},{%8,%9},{%0,%1,%2,%3};"
        : "+f"(d[0]),"+f"(d[1]),"+f"(d[2]),"+f"(d[3])
        : "r"(a[0]),"r"(a[1]),"r"(a[2]),"r"(a[3]),"r"(b0),"r"(b1));
}
__device__ __forceinline__ void cvt2(float ax,float ay,u32&H,u32&L){
    __half2 h=__floats2half2_rn(ax,ay);
    float2 f=__half22float2(h);
    __half2 l=__floats2half2_rn(ax-f.x,ay-f.y);
    H=*(u32*)&h; L=*(u32*)&l;
}

// ---------------- weight conversion pre-pass ----------------
__global__ void conv_main(const float* __restrict__ W, __half* __restrict__ Hh,
                          __half* __restrict__ Hl, int n4){
    int idx=blockIdx.x*blockDim.x+threadIdx.x;
    if(idx>=n4) return;
    float4 v=*(const float4*)(W+(size_t)idx*4);
    u32 h0,l0,h1,l1; cvt2(v.x,v.y,h0,l0); cvt2(v.z,v.w,h1,l1);
    *(uint2*)(Hh+(size_t)idx*4)=make_uint2(h0,h1);
    *(uint2*)(Hl+(size_t)idx*4)=make_uint2(l0,l1);
}
__global__ void conv_gates(const float* __restrict__ W){
    int idx=blockIdx.x*blockDim.x+threadIdx.x;
    if(idx>=NCELL*512*32) return;
    int c4=idx&31; int m=(idx>>5)&511; int k=idx>>14;
    int half=m>>8, mm=m&255, q=mm>>6, gsel=(mm>>5)&1, r=mm&31;
    int base = (half==0) ? (gsel?256:0) : (gsel?384:128);
    int orig = base + 32*q + r;
    float4 v=*(const float4*)(W+(size_t)k*65536+(size_t)orig*128+c4*4);
    u32 h0,l0,h1,l1; cvt2(v.x,v.y,h0,l0); cvt2(v.z,v.w,h1,l1);
    size_t o=(size_t)k*65536+(size_t)m*128+c4*4;
    *(uint2*)(gWGh+o)=make_uint2(h0,h1);
    *(uint2*)(gWGl+o)=make_uint2(l0,l1);
}

// -------- main GEMM: [64,384]x[384,128]^T -> P0 fp32 + bias. K-chunk = 64 --------
__device__ __forceinline__ void main_gemm(char* smc,u32 smb,
    const float* s0,const float* s1,const float* s2,
    const __half* __restrict__ Wh16,const __half* __restrict__ Wl16,
    int b0,int tid,int lane,int w,int biasOff,bool skipPre)
{
    const float* srcs[3]={s0,s1,s2};
    float acc[4][4];
#pragma unroll
    for(int s=0;s<4;s++){acc[s][0]=0;acc[s][1]=0;acc[s][2]=0;acc[s][3]=0;}
    float4 rA[2];
    auto ldA=[&](int kc){
        const float* s=srcs[kc>>1]; int cb=(kc&1)*64;
#pragma unroll
        for(int u=0;u<2;u++){
            int slot=u*CNT+tid; int row=slot>>4; int cq=(slot&15)*4;
            rA[u]= s? *(const float4*)(s+(size_t)(b0+row)*128+cb+cq):make_float4(0,0,0,0);
        }
    };
    auto stsA=[&](int buf){
#pragma unroll
        for(int u=0;u<2;u++){
            int slot=u*CNT+tid; int row=slot>>4; int cq=(slot&15)*4;
            u32 h0,l0,h1,l1; cvt2(rA[u].x,rA[u].y,h0,l0); cvt2(rA[u].z,rA[u].w,h1,l1);
            char* p=smc+AB(buf)+row*144+cq*2;
            *(uint2*)p=make_uint2(h0,h1); *(uint2*)(p+9216)=make_uint2(l0,l1);
        }
    };
    auto cpB=[&](int kc,int buf){
#pragma unroll
        for(int u=0;u<2;u++){
            int idx=u*CNT+tid; int n=idx>>3; int seg=idx&7;
            u32 d=smb+BB(buf)+n*144+seg*16;
            size_t so=(size_t)768*n + 128*kc + 16*seg;
            cpa16(d,(const char*)Wh16+so);
            cpa16(d+18432,(const char*)Wl16+so);
        }
        CP_COMMIT();
    };
    if(!skipPre) cpB(0,0);
    ldA(0); stsA(0); CP_WAIT0(); __syncthreads();
#pragma unroll 1
    for(int kc=0;kc<6;kc++){
        if(kc<5){ cpB(kc+1,(kc+1)&1); ldA(kc+1); }
        const char* Ah=smc+AB(kc&1); const char* Bh=smc+BB(kc&1);
        int ar=16*(w>>2)+(lane>>2);
#pragma unroll
        for(int kh=0;kh<4;kh++){
            int ao=ar*144+(kh*16+(lane&3)*2)*2;
            u32 ah[4],al[4];
            ah[0]=*(const u32*)(Ah+ao);      ah[1]=*(const u32*)(Ah+ao+1152);
            ah[2]=*(const u32*)(Ah+ao+16);   ah[3]=*(const u32*)(Ah+ao+1168);
            al[0]=*(const u32*)(Ah+ao+9216); al[1]=*(const u32*)(Ah+ao+10368);
            al[2]=*(const u32*)(Ah+ao+9232); al[3]=*(const u32*)(Ah+ao+10384);
#pragma unroll
            for(int s=0;s<4;s++){
                int bn=32*(w&3)+8*s+(lane>>2);
                int bo=bn*144+(kh*16+(lane&3)*2)*2;
                u32 bh0=*(const u32*)(Bh+bo),       bh1=*(const u32*)(Bh+bo+16);
                u32 bl0=*(const u32*)(Bh+bo+18432), bl1=*(const u32*)(Bh+bo+18448);
                mma8(acc[s],ah,bh0,bh1);
                mma8(acc[s],ah,bl0,bl1);
                mma8(acc[s],al,bh0,bh1);
            }
        }
        if(kc<5) stsA((kc+1)&1);
        CP_WAIT0();
        __syncthreads();
    }
    float* pcf=(float*)(smc+P0);
    const float* bias=(const float*)(smc+biasOff);
    int r=16*(w>>2)+(lane>>2);
#pragma unroll
    for(int s=0;s<4;s++){
        int c=32*(w&3)+8*s+(lane&3)*2;
        pcf[r*132+c]=acc[s][0]+bias[c];     pcf[r*132+c+1]=acc[s][1]+bias[c+1];
        pcf[(r+8)*132+c]=acc[s][2]+bias[c]; pcf[(r+8)*132+c+1]=acc[s][3]+bias[c+1];
    }
}

__device__ __forceinline__ void ln_pass(char* smc,int lane,int w,int gOff,int bOff,int toHalf){
    float* pcf=(float*)(smc+P0);
    const float* g=(const float*)(smc+gOff); const float* b=(const float*)(smc+bOff);
#pragma unroll 1
    for(int rr=0;rr<4;rr++){
        int r=w*4+rr;
        float v[4];
#pragma unroll
        for(int q=0;q<4;q++) v[q]=pcf[r*132+lane+32*q];
        float s=v[0]+v[1]+v[2]+v[3];
        float qq=v[0]*v[0]+v[1]*v[1]+v[2]*v[2]+v[3]*v[3];
#pragma unroll
        for(int o=16;o;o>>=1){ s+=__shfl_xor_sync(~0u,s,o); qq+=__shfl_xor_sync(~0u,qq,o); }
        float mu=s*(1.f/128.f), var=qq*(1.f/128.f)-mu*mu, rs=rsqrtf(var+LN_EPS);
#pragma unroll
        for(int q=0;q<4;q++){
            float nv=(v[q]-mu)*rs*g[lane+32*q]+b[lane+32*q];
            if(toHalf){
                __half hh=__float2half_rn(nv);
                __half hl=__float2half_rn(nv-__half2float(hh));
                *(__half*)(smc+P1+q*10240+r*80+lane*2)=hh;
                *(__half*)(smc+P1+q*10240+5120+r*80+lane*2)=hl;
            } else pcf[r*132+lane+32*q]=nv;
        }
    }
}

// ---------------- persistent wavefront kernel ----------------
__global__ void __launch_bounds__(CNT,1) cell_kernel(
    const float* __restrict__ x,
    const float* __restrict__ h_ext,const float* __restrict__ c_ext,
    const float* __restrict__ h_grid0,const float* __restrict__ c_grid0,
    const float* __restrict__ bh,const float* __restrict__ bc,
    const float* __restrict__ lnh_g,const float* __restrict__ lnh_b,
    const float* __restrict__ lnc_g,const float* __restrict__ lnc_b,
    const float* __restrict__ W_ih,const float* __restrict__ b_ih,
    const float* __restrict__ b_hh)
{
    extern __shared__ char smc[];
    float* smf=(float*)smc;
    u32 smb=smem_u32(smc);
    int tid=threadIdx.x, lane=tid&31, w=tid>>5;
    __shared__ unsigned int s_task;

    while(true){
        __syncthreads();
        if(tid==0) s_task=atomicAdd(&g_task,1u);
        __syncthreads();
        unsigned int t=s_task;
        if(t>=NTASK) return;

        // task -> (cell c in diagonal order, row block rb) -> k
        int c=t>>6, rb=t&63, b0=rb<<6;
        int d=0, rem=c;
        while(true){ int nc=(d<=8)?(d+1):(17-d); if(rem<nc) break; rem-=nc; d++; }
        int i=(d>8?d-8:0)+rem, j=d-i, k=i*9+j;

        // param loads (independent of deps)
        {
            const float* bihp=b_ih+k*512; const float* bhhp=b_hh+k*512; const float* wihp=W_ih+k*512;
            smf[P_BS/4+tid]=bihp[tid]+bhhp[tid]; smf[P_WIH/4+tid]=wihp[tid];
            if(tid<64) smf[P_X/4+tid]=x[(size_t)(b0+tid)*81+k];
            if(tid>=128&&tid<256){int q=tid-128;
                smf[P_BH/4+q]=bh[k*128+q];    smf[P_BC/4+q]=bc[k*128+q];
                smf[P_LHG/4+q]=lnh_g[k*128+q];smf[P_LHB/4+q]=lnh_b[k*128+q];
                smf[P_LCG/4+q]=lnc_g[k*128+q];smf[P_LCB/4+q]=lnc_b[k*128+q];
            }
        }
        // prefetch h-GEMM weight chunk 0 (independent of deps)
        const __half* WhH=gWHh+(size_t)k*49152;
        const __half* WhL=gWHl+(size_t)k*49152;
        {
#pragma unroll
            for(int u=0;u<2;u++){
                int idx=u*CNT+tid; int n=idx>>3; int seg=idx&7;
                u32 dsm=smb+BB(0)+n*144+seg*16;
                size_t so=(size_t)768*n + 16*seg;
                cpa16(dsm,(const char*)WhH+so);
                cpa16(dsm+18432,(const char*)WhL+so);
            }
            CP_COMMIT();
        }

        // spin on predecessor flags
        if(tid==0 && j>0){
            while(atomicAdd(&g_flag[(k-1)*64+rb],0)==0) __nanosleep(64);
        }
        if(tid==32 && i>0){
            while(atomicAdd(&g_flag[(k-9)*64+rb],0)==0) __nanosleep(64);
        }
        __syncthreads();
        __threadfence();

        const float *h0,*c0,*h1;
        if(j>0){ h0=&g_h[k-1][0][0]; c0=&g_c[k-1][0][0]; }
        else if(i==0){ h0=h_ext; c0=c_ext; }
        else { h0=0; c0=0; }
        h1=(i>0)?&g_h[k-9][0][0]:(const float*)0;
        const float* c1=(i>0)?&g_c[k-9][0][0]:(const float*)0;
        const float* h2=h_grid0+(size_t)k*B_TOT*128;
        const float* c2=c_grid0+(size_t)k*B_TOT*128;

        main_gemm(smc,smb,h0,h1,h2,WhH,WhL,b0,tid,lane,w,P_BH,true);
        __syncthreads();
        ln_pass(smc,lane,w,P_LHG,P_LHB,1);
        __syncthreads();
        main_gemm(smc,smb,c0,c1,c2,gWCh+(size_t)k*49152,gWCl+(size_t)k*49152,b0,tid,lane,w,P_BC,false);
        __syncthreads();
        ln_pass(smc,lane,w,P_LCG,P_LCB,0);
        __syncthreads();

        // ---- gates ----
        const char* Gh=(const char*)(gWGh+(size_t)k*65536);
        const char* Gl=(const char*)(gWGl+(size_t)k*65536);
        float* pcf=(float*)(smc+P0);
        const float* xs=smf+P_X/4;
        int mw=w&3, nw=w>>2;
        float ac0[8][4], ac1[8][4];
#pragma unroll
        for(int s=0;s<8;s++){
            ac0[s][0]=0;ac0[s][1]=0;ac0[s][2]=0;ac0[s][3]=0;
            ac1[s][0]=0;ac1[s][1]=0;ac1[s][2]=0;ac1[s][3]=0;
        }
#pragma unroll
        for(int half=0;half<2;half++){
            float (*ac)[4] = half ? ac1 : ac0;
            const char* GhH=Gh+half*65536;
            const char* GlH=Gl+half*65536;
            auto cpG=[&](int kc,int buf){
#pragma unroll
                for(int u=0;u<2;u++){
                    int idx=u*CNT+tid; int m=idx>>2; int seg=idx&3;
                    u32 dsm=smb+GBUF(buf)+m*80+seg*16;
                    size_t so=(size_t)256*m + 64*kc + 16*seg;
                    cpa16(dsm,GhH+so);
                    cpa16(dsm+20480,GlH+so);
                }
                CP_COMMIT();
            };
            cpG(0,0); CP_WAIT0(); __syncthreads();
#pragma unroll 1
            for(int kc=0;kc<4;kc++){
                if(kc<3) cpG(kc+1,(kc+1)&1);
                const char* Ah=smc+P1+kc*10240; const char* Bh=smc+GBUF(kc&1);
#pragma unroll
                for(int kh=0;kh<2;kh++){
                    int ar=16*mw+(lane>>2);
                    int ao=ar*80+(kh*16+(lane&3)*2)*2;
                    u32 ah[4],al[4];
                    ah[0]=*(const u32*)(Ah+ao);      ah[1]=*(const u32*)(Ah+ao+640);
                    ah[2]=*(const u32*)(Ah+ao+16);   ah[3]=*(const u32*)(Ah+ao+656);
                    al[0]=*(const u32*)(Ah+ao+5120); al[1]=*(const u32*)(Ah+ao+5760);
                    al[2]=*(const u32*)(Ah+ao+5136); al[3]=*(const u32*)(Ah+ao+5776);
#pragma unroll
                    for(int s=0;s<8;s++){
                        int bn=64*nw+8*s+(lane>>2);
                        int bo=bn*80+(kh*16+(lane&3)*2)*2;
                        u32 bh0=*(const u32*)(Bh+bo),       bh1=*(const u32*)(Bh+bo+16);
                        u32 bl0=*(const u32*)(Bh+bo+20480), bl1=*(const u32*)(Bh+bo+20496);
                        mma8(ac[s],ah,bh0,bh1);
                        mma8(ac[s],ah,bl0,bl1);
                        mma8(ac[s],al,bh0,bh1);
                    }
                }
                CP_WAIT0();
                __syncthreads();
            }
        }

        // elementwise LSTM in registers + writeout
#pragma unroll
        for(int s=0;s<4;s++){
#pragma unroll
            for(int rr=0;rr<2;rr++){
                int r2=16*mw+(lane>>2)+rr*8;
                float xv=xs[r2];
#pragma unroll
                for(int e=0;e<2;e++){
                    int cc=32*nw+8*s+(lane&3)*2+e;
                    float I=ac0[s][rr*2+e]  +smf[P_BS/4+cc]      +xv*smf[P_WIH/4+cc];
                    float G=ac0[s+4][rr*2+e]+smf[P_BS/4+256+cc]  +xv*smf[P_WIH/4+256+cc];
                    float F=ac1[s][rr*2+e]  +smf[P_BS/4+128+cc]  +xv*smf[P_WIH/4+128+cc];
                    float O=ac1[s+4][rr*2+e]+smf[P_BS/4+384+cc]  +xv*smf[P_WIH/4+384+cc];
                    float P=pcf[r2*132+cc];
                    float cn=sigmf(F)*P+sigmf(I)*tanhf(G);
                    g_c[k][b0+r2][cc]=cn;
                    g_h[k][b0+r2][cc]=sigmf(O)*tanhf(cn);
                }
            }
        }
        __threadfence();
        __syncthreads();
        if(tid==0) atomicExch(&g_flag[k*64+rb],1);
    }
}

// ---------------- head kernels ----------------
__global__ void z_kernel(const float* __restrict__ h_ext,const float* __restrict__ c_ext){
    int idx=blockIdx.x*256+threadIdx.x;
    int b=idx>>8, c=idx&255;
    float v;
    if(c<128) v=g_h[80][b][c]+h_ext[b*128+c];
    else      v=g_c[80][b][c-128]+c_ext[b*128+c-128];
    g_z[b][c]=v;
}

__global__ void __launch_bounds__(256,1) head_gemm(
    const float* __restrict__ A,const float* __restrict__ W,
    const float* __restrict__ bias,float* __restrict__ C,int N,int K)
{
    __shared__ float A_s[64*33];
    __shared__ float W_s[128*33];
    int tid=threadIdx.x, ty=tid&15, tx=tid>>4;
    int b0=blockIdx.x*64, n0=blockIdx.y*128;
    float acc[4][8];
#pragma unroll
    for(int r=0;r<4;r++)
#pragma unroll
        for(int c=0;c<8;c++) acc[r][c]=0.f;
    int nk=K>>5;
#pragma unroll 1
    for(int kc=0;kc<nk;kc++){
#pragma unroll
        for(int it=0;it<2;it++){
            int idx=it*256+tid; int r=idx>>3; int c4=(idx&7)<<2;
            float4 v=*(const float4*)(A+(size_t)(b0+r)*K+(kc<<5)+c4);
            float* p=&A_s[r*33+c4]; p[0]=v.x;p[1]=v.y;p[2]=v.z;p[3]=v.w;
        }
#pragma unroll
        for(int it=0;it<4;it++){
            int idx=it*256+tid; int n=idx>>3; int c4=(idx&7)<<2;
            float4 v=*(const float4*)(W+(size_t)(n0+n)*K+(kc<<5)+c4);
            float* p=&W_s[n*33+c4]; p[0]=v.x;p[1]=v.y;p[2]=v.z;p[3]=v.w;
        }
        __syncthreads();
#pragma unroll 4
        for(int kk=0;kk<32;kk++){
            float a[4],wv[8];
#pragma unroll
            for(int r=0;r<4;r++) a[r]=A_s[(ty*4+r)*33+kk];
#pragma unroll
            for(int c=0;c<8;c++) wv[c]=W_s[(tx*8+c)*33+kk];
#pragma unroll
            for(int r=0;r<4;r++)
#pragma unroll
                for(int c=0;c<8;c++) acc[r][c]=fmaf(a[r],wv[c],acc[r][c]);
        }
        __syncthreads();
    }
#pragma unroll
    for(int r=0;r<4;r++)
#pragma unroll
        for(int c=0;c<8;c++)
            C[(size_t)(b0+ty*4+r)*N+n0+tx*8+c]=acc[r][c]+bias[n0+tx*8+c];
}

__global__ void bn_stats_kernel(const float* __restrict__ Y,int N){
    __shared__ float ss[256],qq[256];
    int col=blockIdx.x, tid=threadIdx.x;
    float s=0.f,q=0.f;
    for(int r=tid;r<B_TOT;r+=256){ float v=Y[(size_t)r*N+col]; s+=v; q+=v*v; }
    ss[tid]=s; qq[tid]=q; __syncthreads();
    for(int o=128;o;o>>=1){ if(tid<o){ ss[tid]+=ss[tid+o]; qq[tid]+=qq[tid+o]; } __syncthreads(); }
    if(tid==0){
        float mu=ss[0]*(1.f/(float)B_TOT);
        float var=qq[0]*(1.f/(float)B_TOT)-mu*mu;
        g_mu[col]=mu; g_rstd[col]=rsqrtf(var+LN_EPS);
    }
}

__global__ void bn_relu_kernel(float* __restrict__ Y,const float* __restrict__ g,
                               const float* __restrict__ b,int N){
    int idx=blockIdx.x*256+threadIdx.x;
    int c=idx&(N-1);
    float v=(Y[idx]-g_mu[c])*g_rstd[c]*g[c]+b[c];
    Y[idx]=fmaxf(v,0.f);
}

__global__ void fc3_kernel(const float* __restrict__ W,const float* __restrict__ bias){
    int row=(blockIdx.x*blockDim.x+threadIdx.x)>>5;
    int lane=threadIdx.x&31;
    float s=0.f;
#pragma unroll
    for(int c=lane;c<128;c+=32) s+=g_y2[row][c]*W[c];
#pragma unroll
    for(int o=16;o;o>>=1) s+=__shfl_xor_sync(~0u,s,o);
    if(lane==0) g_y3[row]=s+bias[0];
}

__global__ void final_kernel(const float* __restrict__ g,const float* __restrict__ b,
                             float* __restrict__ out){
    __shared__ float ss[1024],qq[1024];
    int tid=threadIdx.x;
    float s=0.f,q=0.f;
    for(int r=tid;r<B_TOT;r+=1024){ float v=g_y3[r]; s+=v; q+=v*v; }
    ss[tid]=s; qq[tid]=q; __syncthreads();
    for(int o=512;o;o>>=1){ if(tid<o){ ss[tid]+=ss[tid+o]; qq[tid]+=qq[tid+o]; } __syncthreads(); }
    float mu=ss[0]*(1.f/(float)B_TOT);
    float var=qq[0]*(1.f/(float)B_TOT)-mu*mu;
    float rs=rsqrtf(var+LN_EPS);
    float gg=g[0], bb=b[0];
    for(int r=tid;r<B_TOT;r+=1024){
        float v=(g_y3[r]-mu)*rs*gg+bb;
        out[r]=1.f/(1.f+expf(-v));
    }
}

extern "C" void kernel_launch(void* const* d_in,const int* in_sizes,int n_in,
                              void* d_out,int out_size)
{
    const float* x     =(const float*)d_in[0];
    const float* h_ext =(const float*)d_in[1];
    const float* c_ext =(const float*)d_in[2];
    const float* h_g0  =(const float*)d_in[3];
    const float* c_g0  =(const float*)d_in[4];
    const float* Wh    =(const float*)d_in[5];
    const float* bh    =(const float*)d_in[6];
    const float* Wc    =(const float*)d_in[7];
    const float* bc    =(const float*)d_in[8];
    const float* lnh_g =(const float*)d_in[9];
    const float* lnh_b =(const float*)d_in[10];
    const float* lnc_g =(const float*)d_in[11];
    const float* lnc_b =(const float*)d_in[12];
    const float* W_ih  =(const float*)d_in[13];
    const float* b_ih  =(const float*)d_in[14];
    const float* W_hh  =(const float*)d_in[15];
    const float* b_hh  =(const float*)d_in[16];
    const float* fc1W  =(const float*)d_in[17];
    const float* fc1b  =(const float*)d_in[18];
    const float* bn1g  =(const float*)d_in[19];
    const float* bn1b  =(const float*)d_in[20];
    const float* fc2W  =(const float*)d_in[21];
    const float* fc2b  =(const float*)d_in[22];
    const float* bn2g  =(const float*)d_in[23];
    const float* bn2b  =(const float*)d_in[24];
    const float* fc3W  =(const float*)d_in[25];
    const float* fc3b  =(const float*)d_in[26];
    const float* bnog  =(const float*)d_in[27];
    const float* bnob  =(const float*)d_in[28];
    float* out=(float*)d_out;

    __half *wHh,*wHl,*wCh,*wCl;
    cudaGetSymbolAddress((void**)&wHh,gWHh); cudaGetSymbolAddress((void**)&wHl,gWHl);
    cudaGetSymbolAddress((void**)&wCh,gWCh); cudaGetSymbolAddress((void**)&wCl,gWCl);
    int n4=NCELL*49152/4;
    conv_main<<<(n4+255)/256,256>>>(Wh,wHh,wHl,n4);
    conv_main<<<(n4+255)/256,256>>>(Wc,wCh,wCl,n4);
    conv_gates<<<(NCELL*512*32+255)/256,256>>>(W_hh);

    // reset flags + task counter (graph-capturable async memsets)
    void *flagPtr,*taskPtr;
    cudaGetSymbolAddress(&flagPtr,g_flag);
    cudaGetSymbolAddress(&taskPtr,g_task);
    cudaMemsetAsync(flagPtr,0,NTASK*sizeof(int));
    cudaMemsetAsync(taskPtr,0,sizeof(unsigned int));

    cudaFuncSetAttribute(cell_kernel, cudaFuncAttributeMaxDynamicSharedMemorySize, SMEM_TOTAL);
    cell_kernel<<<148, CNT, SMEM_TOTAL>>>(
        x,h_ext,c_ext,h_g0,c_g0,bh,bc,
        lnh_g,lnh_b,lnc_g,lnc_b,W_ih,b_ih,b_hh);

    float *zp,*y1p,*y2p;
    cudaGetSymbolAddress((void**)&zp, g_z);
    cudaGetSymbolAddress((void**)&y1p,g_y1);
    cudaGetSymbolAddress((void**)&y2p,g_y2);

    z_kernel<<<4096,256>>>(h_ext,c_ext);
    head_gemm<<<dim3(64,2),256>>>(zp,fc1W,fc1b,y1p,256,256);
    bn_stats_kernel<<<256,256>>>(y1p,256);
    bn_relu_kernel<<<4096,256>>>(y1p,bn1g,bn1b,256);
    head_gemm<<<dim3(64,1),256>>>(y1p,fc2W,fc2b,y2p,128,256);
    bn_stats_kernel<<<128,256>>>(y2p,128);
    bn_relu_kernel<<<2048,256>>>(y2p,bn2g,bn2b,128);
    fc3_kernel<<<512,256>>>(fc3W,fc3b);
    final_kernel<<<1,1024>>>(bnog,bnob,out);
}

// round 17
// speedup vs baseline: 1.6058x; 1.0931x over previous
#include <cuda_runtime.h>
#include <cuda_fp16.h>
#include <cstdint>
typedef uint32_t u32;

#define B_TOT 4096
#define NCELL 81
#define LN_EPS 1e-5f
#define CNT 512
#define NTASK (NCELL*64)

__device__ float g_h[NCELL][B_TOT][128];
__device__ float g_c[NCELL][B_TOT][128];
__device__ float g_z [B_TOT][256];
__device__ float g_y1[B_TOT][256];
__device__ float g_y2[B_TOT][128];
__device__ float g_y3[B_TOT];
__device__ float g_mu[256];
__device__ float g_rstd[256];
__device__ int g_flag[NTASK];
__device__ unsigned int g_task;

// fragment-ordered fp16 hi/lo weights
__device__ __half gWHh[NCELL*49152], gWHl[NCELL*49152];
__device__ __half gWCh[NCELL*49152], gWCl[NCELL*49152];
__device__ __half gWGh[NCELL*65536], gWGl[NCELL*65536];

__device__ __forceinline__ float sigmf(float v){ return 1.f/(1.f+expf(-v)); }
__device__ __forceinline__ u32 smem_u32(const void* p){
    u32 a; asm("{ .reg .u64 t; cvta.to.shared.u64 t, %1; cvt.u32.u64 %0, t; }" : "=r"(a) : "l"(p)); return a;
}
__device__ __forceinline__ void cpa16(u32 dst, const void* src){
    asm volatile("cp.async.ca.shared.global [%0], [%1], 16;"::"r"(dst),"l"(src));
}
#define CP_COMMIT() asm volatile("cp.async.commit_group;":::"memory")
#define CP_WAIT0()  asm volatile("cp.async.wait_group 0;":::"memory")

// ---- smem byte offsets (64-row CTA) ----
#define P_BS  0
#define P_WIH 2048
#define P_X   4096
#define P_BH  4352
#define P_BC  4864
#define P_LHG 5376
#define P_LHB 5888
#define P_LCG 6400
#define P_LCB 6912
#define P0    7424                    // fp32 staging 64 x 132 = 33792B
#define P1    41216                   // gates A frag: 4 chunks x (4096 hi + 4096 lo) = 32768B
#define P2    73984                   // overlay: main A/B | gates B
#define SMEM_TOTAL 172288
#define AB(i)   (P2 + (i)*16384)              // A frag: 8192 hi, lo +8192
#define BB(i)   (P2 + 32768 + (i)*32768)      // B frag: 16384 hi, lo +16384
#define GBUF(i) (P2 + (i)*32768)              // gates B frag: 16384 hi, lo +16384

__device__ __forceinline__ void mma8(float* d,const u32* a,u32 b0,u32 b1){
    asm volatile("mma.sync.aligned.m16n8k16.row.col.f32.f16.f16.f32 "
        "{%0,%1,%2,%3},{%4,%5,%6,%7},{%8,%9},{%0,%1,%2,%3};"
        : "+f"(d[0]),"+f"(d[1]),"+f"(d[2]),"+f"(d[3])
        : "r"(a[0]),"r"(a[1]),"r"(a[2]),"r"(a[3]),"r"(b0),"r"(b1));
}
__device__ __forceinline__ void cvt2(float ax,float ay,u32&H,u32&L){
    __half2 h=__floats2half2_rn(ax,ay);
    float2 f=__half22float2(h);
    __half2 l=__floats2half2_rn(ax-f.x,ay-f.y);
    H=*(u32*)&h; L=*(u32*)&l;
}

// ---------- weight conversion: fragment-order layouts ----------
// main weights: per cell, per chunk kc(64k): [nt 0..15][kh 0..3][lane 0..31][b0,b1]
__global__ void conv_main(const float* __restrict__ W, __half* __restrict__ Hh,
                          __half* __restrict__ Hl, int nU){
    int idx=blockIdx.x*blockDim.x+threadIdx.x;
    if(idx>=nU) return;                      // u32 units
    int cell=idx/24576, rem=idx%24576;
    int kc=rem>>12, r2=rem&4095;
    int nt=r2>>8, r3=r2&255;
    int kh=r3>>6, r4=r3&63;
    int lane=r4>>1, bsel=r4&1;
    int n=nt*8+(lane>>2);
    int kk=kc*64+kh*16+bsel*8+(lane&3)*2;
    const float* src=W+(size_t)cell*49152+(size_t)n*384+kk;
    u32 H,L; cvt2(src[0],src[1],H,L);
    *(u32*)((char*)Hh+(size_t)idx*4)=H;
    *(u32*)((char*)Hl+(size_t)idx*4)=L;
}
// gates: per cell: [half][kc(32k)][nt 0..31][kh 0..1][lane][b0,b1], rows permuted
__global__ void conv_gates(const float* __restrict__ W, int nU){
    int idx=blockIdx.x*blockDim.x+threadIdx.x;
    if(idx>=nU) return;
    int cell=idx/32768, rem=idx%32768;
    int half=rem>>14, r1=rem&16383;
    int kc=r1>>12, r2=r1&4095;
    int nt=r2>>7, r3=r2&127;
    int kh=r3>>6, r4=r3&63;
    int lane=r4>>1, bsel=r4&1;
    int m=nt*8+(lane>>2);
    int q=m>>6, gsel=(m>>5)&1, r=m&31;
    int base=(half==0)?(gsel?256:0):(gsel?384:128);
    int orig=base+32*q+r;
    int kk=kc*32+kh*16+bsel*8+(lane&3)*2;
    const float* src=W+(size_t)cell*65536+(size_t)orig*128+kk;
    u32 H,L; cvt2(src[0],src[1],H,L);
    *(u32*)((char*)gWGh+(size_t)idx*4)=H;
    *(u32*)((char*)gWGl+(size_t)idx*4)=L;
}

// -------- main GEMM: [64,384]x[384,128]^T -> P0 fp32 + bias. K-chunk = 64 --------
__device__ __forceinline__ void main_gemm(char* smc,u32 smb,
    const float* s0,const float* s1,const float* s2,
    const __half* __restrict__ Wh16,const __half* __restrict__ Wl16,
    int b0,int tid,int lane,int w,int biasOff,bool skipPre)
{
    const float* srcs[3]={s0,s1,s2};
    float acc[4][4];
#pragma unroll
    for(int s=0;s<4;s++){acc[s][0]=0;acc[s][1]=0;acc[s][2]=0;acc[s][3]=0;}
    float4 rA[2];
    auto ldA=[&](int kc){
        const float* s=srcs[kc>>1]; int cb=(kc&1)*64;
#pragma unroll
        for(int u=0;u<2;u++){
            int slot=u*CNT+tid; int row=slot>>4; int cq=(slot&15)*4;
            rA[u]= s? *(const float4*)(s+(size_t)(b0+row)*128+cb+cq):make_float4(0,0,0,0);
        }
    };
    auto stsA=[&](int buf){
#pragma unroll
        for(int u=0;u<2;u++){
            int slot=u*CNT+tid; int row=slot>>4; int cq=(slot&15)*4;
            u32 H0,L0,H1,L1; cvt2(rA[u].x,rA[u].y,H0,L0); cvt2(rA[u].z,rA[u].w,H1,L1);
            int g=row&15, mt=row>>4;
            int rsel=(g>=8)?1:0, lf=(g&7)*4;
#pragma unroll
            for(int up=0;up<2;up++){
                int kp=cq+2*up;
                int kh=kp>>4, rr=kp&15;
                int asel=(rr>=8)?2:0, k2=(rr&7)>>1;
                u32 off=AB(buf)+(((mt*4+kh)*32+lf+k2)<<4)+((asel+rsel)<<2);
                *(u32*)(smc+off)=up?H1:H0;
                *(u32*)(smc+off+8192)=up?L1:L0;
            }
        }
    };
    auto cpB=[&](int kc,int buf){
#pragma unroll
        for(int u=0;u<2;u++){
            int idx=u*CNT+tid;
            u32 d=smb+BB(buf)+idx*16;
            size_t so=(size_t)kc*16384+(size_t)idx*16;
            cpa16(d,(const char*)Wh16+so);
            cpa16(d+16384,(const char*)Wl16+so);
        }
        CP_COMMIT();
    };
    if(!skipPre) cpB(0,0);
    ldA(0); stsA(0); CP_WAIT0(); __syncthreads();
#pragma unroll 1
    for(int kc=0;kc<6;kc++){
        if(kc<5){ cpB(kc+1,(kc+1)&1); ldA(kc+1); }
        const char* Ah=smc+AB(kc&1); const char* Bh=smc+BB(kc&1);
        int mt=w>>2, ng=w&3;
#pragma unroll
        for(int kh=0;kh<4;kh++){
            uint4 AH=*(const uint4*)(Ah+(((mt*4+kh)*32+lane)<<4));
            uint4 AL=*(const uint4*)(Ah+8192+(((mt*4+kh)*32+lane)<<4));
#pragma unroll
            for(int s=0;s<4;s++){
                int nt=4*ng+s;
                uint2 BH=*(const uint2*)(Bh+(((nt*4+kh)*32+lane)<<3));
                uint2 BL=*(const uint2*)(Bh+16384+(((nt*4+kh)*32+lane)<<3));
                mma8(acc[s],(const u32*)&AH,BH.x,BH.y);
                mma8(acc[s],(const u32*)&AH,BL.x,BL.y);
                mma8(acc[s],(const u32*)&AL,BH.x,BH.y);
            }
        }
        if(kc<5) stsA((kc+1)&1);
        CP_WAIT0();
        __syncthreads();
    }
    float* pcf=(float*)(smc+P0);
    const float* bias=(const float*)(smc+biasOff);
    int r=16*(w>>2)+(lane>>2);
#pragma unroll
    for(int s=0;s<4;s++){
        int c=32*(w&3)+8*s+(lane&3)*2;
        pcf[r*132+c]=acc[s][0]+bias[c];     pcf[r*132+c+1]=acc[s][1]+bias[c+1];
        pcf[(r+8)*132+c]=acc[s][2]+bias[c]; pcf[(r+8)*132+c+1]=acc[s][3]+bias[c+1];
    }
}

// LN over P0; 16 warps x 4 rows; toHalf writes gates-A fragments into P1
__device__ __forceinline__ void ln_pass(char* smc,int lane,int w,int gOff,int bOff,int toHalf){
    float* pcf=(float*)(smc+P0);
    const float* g=(const float*)(smc+gOff); const float* b=(const float*)(smc+bOff);
#pragma unroll 1
    for(int rr=0;rr<4;rr++){
        int r=w*4+rr;
        float2 v0=*(const float2*)(pcf+r*132+2*lane);
        float2 v1=*(const float2*)(pcf+r*132+64+2*lane);
        float s=v0.x+v0.y+v1.x+v1.y;
        float qq=v0.x*v0.x+v0.y*v0.y+v1.x*v1.x+v1.y*v1.y;
#pragma unroll
        for(int o=16;o;o>>=1){ s+=__shfl_xor_sync(~0u,s,o); qq+=__shfl_xor_sync(~0u,qq,o); }
        float mu=s*(1.f/128.f), var=qq*(1.f/128.f)-mu*mu, rs=rsqrtf(var+LN_EPS);
#pragma unroll
        for(int q=0;q<2;q++){
            float2 vv=q?v1:v0;
            int c0=2*lane+64*q;
            float n0=(vv.x-mu)*rs*g[c0]+b[c0];
            float n1=(vv.y-mu)*rs*g[c0+1]+b[c0+1];
            if(toHalf){
                u32 H,L; cvt2(n0,n1,H,L);
                int kcc=(lane>>4)+2*q;
                int kh=(lane>>3)&1;
                int asel=((lane>>2)&1)?2:0;
                int k2=lane&3;
                int g2=r&15, mt=r>>4;
                int aidx=asel+((g2>=8)?1:0);
                u32 off=P1+kcc*8192+(((mt*2+kh)*32+(g2&7)*4+k2)<<4)+(aidx<<2);
                *(u32*)(smc+off)=H;
                *(u32*)(smc+off+4096)=L;
            } else {
                pcf[r*132+c0]=n0; pcf[r*132+c0+1]=n1;
            }
        }
    }
}

// ---------------- persistent wavefront kernel ----------------
__global__ void __launch_bounds__(CNT,1) cell_kernel(
    const float* __restrict__ x,
    const float* __restrict__ h_ext,const float* __restrict__ c_ext,
    const float* __restrict__ h_grid0,const float* __restrict__ c_grid0,
    const float* __restrict__ bh,const float* __restrict__ bc,
    const float* __restrict__ lnh_g,const float* __restrict__ lnh_b,
    const float* __restrict__ lnc_g,const float* __restrict__ lnc_b,
    const float* __restrict__ W_ih,const float* __restrict__ b_ih,
    const float* __restrict__ b_hh)
{
    extern __shared__ char smc[];
    float* smf=(float*)smc;
    u32 smb=smem_u32(smc);
    int tid=threadIdx.x, lane=tid&31, w=tid>>5;
    __shared__ unsigned int s_task;

    while(true){
        __syncthreads();
        if(tid==0) s_task=atomicAdd(&g_task,1u);
        __syncthreads();
        unsigned int t=s_task;
        if(t>=NTASK) return;

        int c=t>>6, rb=t&63, b0=rb<<6;
        int d=0, rem=c;
        while(true){ int nc=(d<=8)?(d+1):(17-d); if(rem<nc) break; rem-=nc; d++; }
        int i=(d>8?d-8:0)+rem, j=d-i, k=i*9+j;

        {
            const float* bihp=b_ih+k*512; const float* bhhp=b_hh+k*512; const float* wihp=W_ih+k*512;
            smf[P_BS/4+tid]=bihp[tid]+bhhp[tid]; smf[P_WIH/4+tid]=wihp[tid];
            if(tid<64) smf[P_X/4+tid]=x[(size_t)(b0+tid)*81+k];
            if(tid>=128&&tid<256){int q=tid-128;
                smf[P_BH/4+q]=bh[k*128+q];    smf[P_BC/4+q]=bc[k*128+q];
                smf[P_LHG/4+q]=lnh_g[k*128+q];smf[P_LHB/4+q]=lnh_b[k*128+q];
                smf[P_LCG/4+q]=lnc_g[k*128+q];smf[P_LCB/4+q]=lnc_b[k*128+q];
            }
        }
        const __half* WhH=gWHh+(size_t)k*49152;
        const __half* WhL=gWHl+(size_t)k*49152;
        {
#pragma unroll
            for(int u=0;u<2;u++){
                int idx=u*CNT+tid;
                u32 dsm=smb+BB(0)+idx*16;
                size_t so=(size_t)idx*16;
                cpa16(dsm,(const char*)WhH+so);
                cpa16(dsm+16384,(const char*)WhL+so);
            }
            CP_COMMIT();
        }

        if(tid==0 && j>0){
            while(atomicAdd(&g_flag[(k-1)*64+rb],0)==0) __nanosleep(64);
        }
        if(tid==32 && i>0){
            while(atomicAdd(&g_flag[(k-9)*64+rb],0)==0) __nanosleep(64);
        }
        __syncthreads();
        __threadfence();

        const float *h0,*c0,*h1;
        if(j>0){ h0=&g_h[k-1][0][0]; c0=&g_c[k-1][0][0]; }
        else if(i==0){ h0=h_ext; c0=c_ext; }
        else { h0=0; c0=0; }
        h1=(i>0)?&g_h[k-9][0][0]:(const float*)0;
        const float* c1=(i>0)?&g_c[k-9][0][0]:(const float*)0;
        const float* h2=h_grid0+(size_t)k*B_TOT*128;
        const float* c2=c_grid0+(size_t)k*B_TOT*128;

        main_gemm(smc,smb,h0,h1,h2,WhH,WhL,b0,tid,lane,w,P_BH,true);
        __syncthreads();
        ln_pass(smc,lane,w,P_LHG,P_LHB,1);
        __syncthreads();
        main_gemm(smc,smb,c0,c1,c2,gWCh+(size_t)k*49152,gWCl+(size_t)k*49152,b0,tid,lane,w,P_BC,false);
        __syncthreads();
        ln_pass(smc,lane,w,P_LCG,P_LCB,0);
        __syncthreads();

        // ---- gates ----
        const char* Gh=(const char*)(gWGh+(size_t)k*65536);
        const char* Gl=(const char*)(gWGl+(size_t)k*65536);
        float* pcf=(float*)(smc+P0);
        const float* xs=smf+P_X/4;
        int mw=w&3, nw=w>>2;
        float ac0[8][4], ac1[8][4];
#pragma unroll
        for(int s=0;s<8;s++){
            ac0[s][0]=0;ac0[s][1]=0;ac0[s][2]=0;ac0[s][3]=0;
            ac1[s][0]=0;ac1[s][1]=0;ac1[s][2]=0;ac1[s][3]=0;
        }
#pragma unroll
        for(int half=0;half<2;half++){
            float (*ac)[4] = half ? ac1 : ac0;
            const char* GhH=Gh+half*65536;
            const char* GlH=Gl+half*65536;
            auto cpG=[&](int kc,int buf){
#pragma unroll
                for(int u=0;u<2;u++){
                    int idx=u*CNT+tid;
                    u32 dsm=smb+GBUF(buf)+idx*16;
                    size_t so=(size_t)kc*16384+(size_t)idx*16;
                    cpa16(dsm,GhH+so);
                    cpa16(dsm+16384,GlH+so);
                }
                CP_COMMIT();
            };
            cpG(0,0); CP_WAIT0(); __syncthreads();
#pragma unroll 1
            for(int kc=0;kc<4;kc++){
                if(kc<3) cpG(kc+1,(kc+1)&1);
                const char* Ah=smc+P1+kc*8192; const char* Bh=smc+GBUF(kc&1);
#pragma unroll
                for(int kh=0;kh<2;kh++){
                    uint4 AH=*(const uint4*)(Ah+(((mw*2+kh)*32+lane)<<4));
                    uint4 AL=*(const uint4*)(Ah+4096+(((mw*2+kh)*32+lane)<<4));
#pragma unroll
                    for(int s=0;s<8;s++){
                        int nt=8*nw+s;
                        uint2 BH=*(const uint2*)(Bh+(((nt*2+kh)*32+lane)<<3));
                        uint2 BL=*(const uint2*)(Bh+16384+(((nt*2+kh)*32+lane)<<3));
                        mma8(ac[s],(const u32*)&AH,BH.x,BH.y);
                        mma8(ac[s],(const u32*)&AH,BL.x,BL.y);
                        mma8(ac[s],(const u32*)&AL,BH.x,BH.y);
                    }
                }
                CP_WAIT0();
                __syncthreads();
            }
        }

        // elementwise LSTM in registers + writeout
#pragma unroll
        for(int s=0;s<4;s++){
#pragma unroll
            for(int rr=0;rr<2;rr++){
                int r2=16*mw+(lane>>2)+rr*8;
                float xv=xs[r2];
#pragma unroll
                for(int e=0;e<2;e++){
                    int cc=32*nw+8*s+(lane&3)*2+e;
                    float I=ac0[s][rr*2+e]  +smf[P_BS/4+cc]      +xv*smf[P_WIH/4+cc];
                    float G=ac0[s+4][rr*2+e]+smf[P_BS/4+256+cc]  +xv*smf[P_WIH/4+256+cc];
                    float F=ac1[s][rr*2+e]  +smf[P_BS/4+128+cc]  +xv*smf[P_WIH/4+128+cc];
                    float O=ac1[s+4][rr*2+e]+smf[P_BS/4+384+cc]  +xv*smf[P_WIH/4+384+cc];
                    float P=pcf[r2*132+cc];
                    float cn=sigmf(F)*P+sigmf(I)*tanhf(G);
                    g_c[k][b0+r2][cc]=cn;
                    g_h[k][b0+r2][cc]=sigmf(O)*tanhf(cn);
                }
            }
        }
        __threadfence();
        __syncthreads();
        if(tid==0) atomicExch(&g_flag[k*64+rb],1);
    }
}

// ---------------- head kernels ----------------
__global__ void z_kernel(const float* __restrict__ h_ext,const float* __restrict__ c_ext){
    int idx=blockIdx.x*256+threadIdx.x;
    int b=idx>>8, c=idx&255;
    float v;
    if(c<128) v=g_h[80][b][c]+h_ext[b*128+c];
    else      v=g_c[80][b][c-128]+c_ext[b*128+c-128];
    g_z[b][c]=v;
}

__global__ void __launch_bounds__(256,1) head_gemm(
    const float* __restrict__ A,const float* __restrict__ W,
    const float* __restrict__ bias,float* __restrict__ C,int N,int K)
{
    __shared__ float A_s[64*33];
    __shared__ float W_s[128*33];
    int tid=threadIdx.x, ty=tid&15, tx=tid>>4;
    int b0=blockIdx.x*64, n0=blockIdx.y*128;
    float acc[4][8];
#pragma unroll
    for(int r=0;r<4;r++)
#pragma unroll
        for(int c=0;c<8;c++) acc[r][c]=0.f;
    int nk=K>>5;
#pragma unroll 1
    for(int kc=0;kc<nk;kc++){
#pragma unroll
        for(int it=0;it<2;it++){
            int idx=it*256+tid; int r=idx>>3; int c4=(idx&7)<<2;
            float4 v=*(const float4*)(A+(size_t)(b0+r)*K+(kc<<5)+c4);
            float* p=&A_s[r*33+c4]; p[0]=v.x;p[1]=v.y;p[2]=v.z;p[3]=v.w;
        }
#pragma unroll
        for(int it=0;it<4;it++){
            int idx=it*256+tid; int n=idx>>3; int c4=(idx&7)<<2;
            float4 v=*(const float4*)(W+(size_t)(n0+n)*K+(kc<<5)+c4);
            float* p=&W_s[n*33+c4]; p[0]=v.x;p[1]=v.y;p[2]=v.z;p[3]=v.w;
        }
        __syncthreads();
#pragma unroll 4
        for(int kk=0;kk<32;kk++){
            float a[4],wv[8];
#pragma unroll
            for(int r=0;r<4;r++) a[r]=A_s[(ty*4+r)*33+kk];
#pragma unroll
            for(int c=0;c<8;c++) wv[c]=W_s[(tx*8+c)*33+kk];
#pragma unroll
            for(int r=0;r<4;r++)
#pragma unroll
                for(int c=0;c<8;c++) acc[r][c]=fmaf(a[r],wv[c],acc[r][c]);
        }
        __syncthreads();
    }
#pragma unroll
    for(int r=0;r<4;r++)
#pragma unroll
        for(int c=0;c<8;c++)
            C[(size_t)(b0+ty*4+r)*N+n0+tx*8+c]=acc[r][c]+bias[n0+tx*8+c];
}

__global__ void bn_stats_kernel(const float* __restrict__ Y,int N){
    __shared__ float ss[256],qq[256];
    int col=blockIdx.x, tid=threadIdx.x;
    float s=0.f,q=0.f;
    for(int r=tid;r<B_TOT;r+=256){ float v=Y[(size_t)r*N+col]; s+=v; q+=v*v; }
    ss[tid]=s; qq[tid]=q; __syncthreads();
    for(int o=128;o;o>>=1){ if(tid<o){ ss[tid]+=ss[tid+o]; qq[tid]+=qq[tid+o]; } __syncthreads(); }
    if(tid==0){
        float mu=ss[0]*(1.f/(float)B_TOT);
        float var=qq[0]*(1.f/(float)B_TOT)-mu*mu;
        g_mu[col]=mu; g_rstd[col]=rsqrtf(var+LN_EPS);
    }
}

__global__ void bn_relu_kernel(float* __restrict__ Y,const float* __restrict__ g,
                               const float* __restrict__ b,int N){
    int idx=blockIdx.x*256+threadIdx.x;
    int c=idx&(N-1);
    float v=(Y[idx]-g_mu[c])*g_rstd[c]*g[c]+b[c];
    Y[idx]=fmaxf(v,0.f);
}

__global__ void fc3_kernel(const float* __restrict__ W,const float* __restrict__ bias){
    int row=(blockIdx.x*blockDim.x+threadIdx.x)>>5;
    int lane=threadIdx.x&31;
    float s=0.f;
#pragma unroll
    for(int c=lane;c<128;c+=32) s+=g_y2[row][c]*W[c];
#pragma unroll
    for(int o=16;o;o>>=1) s+=__shfl_xor_sync(~0u,s,o);
    if(lane==0) g_y3[row]=s+bias[0];
}

__global__ void final_kernel(const float* __restrict__ g,const float* __restrict__ b,
                             float* __restrict__ out){
    __shared__ float ss[1024],qq[1024];
    int tid=threadIdx.x;
    float s=0.f,q=0.f;
    for(int r=tid;r<B_TOT;r+=1024){ float v=g_y3[r]; s+=v; q+=v*v; }
    ss[tid]=s; qq[tid]=q; __syncthreads();
    for(int o=512;o;o>>=1){ if(tid<o){ ss[tid]+=ss[tid+o]; qq[tid]+=qq[tid+o]; } __syncthreads(); }
    float mu=ss[0]*(1.f/(float)B_TOT);
    float var=qq[0]*(1.f/(float)B_TOT)-mu*mu;
    float rs=rsqrtf(var+LN_EPS);
    float gg=g[0], bb=b[0];
    for(int r=tid;r<B_TOT;r+=1024){
        float v=(g_y3[r]-mu)*rs*gg+bb;
        out[r]=1.f/(1.f+expf(-v));
    }
}

extern "C" void kernel_launch(void* const* d_in,const int* in_sizes,int n_in,
                              void* d_out,int out_size)
{
    const float* x     =(const float*)d_in[0];
    const float* h_ext =(const float*)d_in[1];
    const float* c_ext =(const float*)d_in[2];
    const float* h_g0  =(const float*)d_in[3];
    const float* c_g0  =(const float*)d_in[4];
    const float* Wh    =(const float*)d_in[5];
    const float* bh    =(const float*)d_in[6];
    const float* Wc    =(const float*)d_in[7];
    const float* bc    =(const float*)d_in[8];
    const float* lnh_g =(const float*)d_in[9];
    const float* lnh_b =(const float*)d_in[10];
    const float* lnc_g =(const float*)d_in[11];
    const float* lnc_b =(const float*)d_in[12];
    const float* W_ih  =(const float*)d_in[13];
    const float* b_ih  =(const float*)d_in[14];
    const float* W_hh  =(const float*)d_in[15];
    const float* b_hh  =(const float*)d_in[16];
    const float* fc1W  =(const float*)d_in[17];
    const float* fc1b  =(const float*)d_in[18];
    const float* bn1g  =(const float*)d_in[19];
    const float* bn1b  =(const float*)d_in[20];
    const float* fc2W  =(const float*)d_in[21];
    const float* fc2b  =(const float*)d_in[22];
    const float* bn2g  =(const float*)d_in[23];
    const float* bn2b  =(const float*)d_in[24];
    const float* fc3W  =(const float*)d_in[25];
    const float* fc3b  =(const float*)d_in[26];
    const float* bnog  =(const float*)d_in[27];
    const float* bnob  =(const float*)d_in[28];
    float* out=(float*)d_out;

    __half *wHh,*wHl,*wCh,*wCl;
    cudaGetSymbolAddress((void**)&wHh,gWHh); cudaGetSymbolAddress((void**)&wHl,gWHl);
    cudaGetSymbolAddress((void**)&wCh,gWCh); cudaGetSymbolAddress((void**)&wCl,gWCl);
    int nU=NCELL*24576;
    conv_main<<<(nU+255)/256,256>>>(Wh,wHh,wHl,nU);
    conv_main<<<(nU+255)/256,256>>>(Wc,wCh,wCl,nU);
    int nG=NCELL*32768;
    conv_gates<<<(nG+255)/256,256>>>(W_hh,nG);

    void *flagPtr,*taskPtr;
    cudaGetSymbolAddress(&flagPtr,g_flag);
    cudaGetSymbolAddress(&taskPtr,g_task);
    cudaMemsetAsync(flagPtr,0,NTASK*sizeof(int));
    cudaMemsetAsync(taskPtr,0,sizeof(unsigned int));

    cudaFuncSetAttribute(cell_kernel, cudaFuncAttributeMaxDynamicSharedMemorySize, SMEM_TOTAL);
    cell_kernel<<<148, CNT, SMEM_TOTAL>>>(
        x,h_ext,c_ext,h_g0,c_g0,bh,bc,
        lnh_g,lnh_b,lnc_g,lnc_b,W_ih,b_ih,b_hh);

    float *zp,*y1p,*y2p;
    cudaGetSymbolAddress((void**)&zp, g_z);
    cudaGetSymbolAddress((void**)&y1p,g_y1);
    cudaGetSymbolAddress((void**)&y2p,g_y2);

    z_kernel<<<4096,256>>>(h_ext,c_ext);
    head_gemm<<<dim3(64,2),256>>>(zp,fc1W,fc1b,y1p,256,256);
    bn_stats_kernel<<<256,256>>>(y1p,256);
    bn_relu_kernel<<<4096,256>>>(y1p,bn1g,bn1b,256);
    head_gemm<<<dim3(64,1),256>>>(y1p,fc2W,fc2b,y2p,128,256);
    bn_stats_kernel<<<128,256>>>(y2p,128);
    bn_relu_kernel<<<2048,256>>>(y2p,bn2g,bn2b,128);
    fc3_kernel<<<512,256>>>(fc3W,fc3b);
    final_kernel<<<1,1024>>>(bnog,bnob,out);
}